// round 3
// baseline (speedup 1.0000x reference)
#include <cuda_runtime.h>

// Problem constants
#define NC    188   // nodes
#define PF    16    // features per node
#define HID   128   // hidden
#define H2    64    // hidden/2
#define DE    5     // edge effect dim
#define DOUT  6     // object output dim
#define NT    5     // targets
#define BATCH 32
#define TPB   192   // 6 warps
#define DSP   192   // padded row length for DS
#define CH    16    // i-chunk of DS staged in smem per step

// Scratch
__device__ float g_O[BATCH * NC * DOUT];
__device__ float g_DR[BATCH * NC * HID];     // b1 + xr . W1[0:16,:]   [b][r][i]
__device__ float g_DS[BATCH * HID * DSP];    // xs . W1[16:32,:]        [b][i][s]

// ---- packed f32x2 helpers ----
__device__ __forceinline__ unsigned long long pk2(float lo, float hi) {
    unsigned long long r;
    asm("mov.b64 %0, {%1, %2};" : "=l"(r) : "f"(lo), "f"(hi));
    return r;
}
__device__ __forceinline__ float2 upk2(unsigned long long v) {
    float2 f;
    asm("mov.b64 {%0, %1}, %2;" : "=f"(f.x), "=f"(f.y) : "l"(v));
    return f;
}
__device__ __forceinline__ void fma2(unsigned long long& d,
                                     unsigned long long a,
                                     unsigned long long b) {
    asm("fma.rn.f32x2 %0, %1, %2, %0;" : "+l"(d) : "l"(a), "l"(b));
}

// ============================================================================
// Kernel P: per-node layer-1 half-dots. grid (NC, BATCH), 128 threads.
// ============================================================================
__global__ void __launch_bounds__(HID) precompute_kernel(
    const float* __restrict__ x,
    const float* __restrict__ fr1_w, const float* __restrict__ fr1_b)
{
    __shared__ float SX[PF];
    const int n = blockIdx.x, b = blockIdx.y, i = threadIdx.x;
    if (i < PF) SX[i] = x[((size_t)b * NC + n) * PF + i];
    __syncthreads();
    float dr = fr1_b[i], ds = 0.f;
    #pragma unroll
    for (int m = 0; m < PF; m++) {
        float xm = SX[m];
        dr = fmaf(xm, fr1_w[m * HID + i], dr);
        ds = fmaf(xm, fr1_w[(PF + m) * HID + i], ds);
    }
    g_DR[((size_t)b * NC + n) * HID + i] = dr;
    g_DS[((size_t)b * HID + i) * DSP + n] = ds;
}

// ============================================================================
// Kernel A: one block per (receiver r, batch b).
// Register-tiled layer-2 GEMM: thread = 4 senders x 16 h2-outputs.
// Lane layout: lane = 4*quad_local + ngroup  (4 output-groups of an edge-quad
// are adjacent lanes -> layer-3 reduction via shfl).
// All 188 senders computed (incl. s==r), s==r masked in the reduction.
// ============================================================================
__global__ void __launch_bounds__(TPB, 2) edge_obj_kernel(
    const float* __restrict__ x,
    const float* __restrict__ fr2_w, const float* __restrict__ fr2_b,
    const float* __restrict__ fr3_w, const float* __restrict__ fr3_b,
    const float* __restrict__ fo1_w, const float* __restrict__ fo1_b,
    const float* __restrict__ fo2_w, const float* __restrict__ fo2_b,
    const float* __restrict__ fo3_w, const float* __restrict__ fo3_b)
{
    __shared__ __align__(16) float SW2[HID * H2];    // 32 KB, row i = 64 floats
    __shared__ __align__(16) float SDS[CH * DSP];    // 12 KB chunk of DS
    __shared__ float SW3[H2 * DE];                   // fr3 natural [o][k]
    __shared__ float SDR[HID];
    __shared__ float SXR[PF];
    __shared__ float SB3[8];
    __shared__ float SRED[6 * DE];
    __shared__ float SEBAR[8];
    __shared__ float SH1[HID];
    __shared__ float SH2v[H2];

    const int r    = blockIdx.x;
    const int b    = blockIdx.y;
    const int tid  = threadIdx.x;
    const int w    = tid >> 5;
    const int lane = tid & 31;
    const int ml   = lane >> 2;        // quad within warp 0..7
    const int n    = lane & 3;         // output group 0..3 (16 outputs each)
    const int m    = (w << 3) + ml;    // sender quad 0..47
    const bool active = (m < 47);      // quads 0..46 cover senders 0..187

    // ---- staging ----
    {
        const float4* s4 = reinterpret_cast<const float4*>(fr2_w);
        float4* d4 = reinterpret_cast<float4*>(SW2);
        #pragma unroll 4
        for (int idx = tid; idx < HID * H2 / 4; idx += TPB) d4[idx] = s4[idx];
    }
    for (int idx = tid; idx < H2 * DE; idx += TPB) SW3[idx] = fr3_w[idx];
    if (tid < HID) SDR[tid] = g_DR[((size_t)b * NC + r) * HID + tid];
    if (tid < PF)  SXR[tid] = x[((size_t)b * NC + r) * PF + tid];
    if (tid < DE)  SB3[tid] = fr3_b[tid];

    // acc[e][q]: 4 edges x 8 packed pairs (16 outputs), init with fr2 bias
    unsigned long long acc[32];
    {
        const float2* b2 = reinterpret_cast<const float2*>(fr2_b + (n << 4));
        #pragma unroll
        for (int q = 0; q < 8; q++) {
            float2 bb = b2[q];
            unsigned long long v = pk2(bb.x, bb.y);
            acc[q] = v; acc[8 + q] = v; acc[16 + q] = v; acc[24 + q] = v;
        }
    }

    // ---- main k-loop over layer-1 hidden units, chunked DS staging ----
    for (int c = 0; c < HID / CH; c++) {
        __syncthreads();
        const float4* src = reinterpret_cast<const float4*>(
            g_DS + ((size_t)b * HID + c * CH) * DSP);
        float4* dst = reinterpret_cast<float4*>(SDS);
        #pragma unroll
        for (int q = tid; q < CH * DSP / 4; q += TPB) dst[q] = src[q];
        __syncthreads();

        if (active) {
            #pragma unroll
            for (int ii = 0; ii < CH; ii++) {
                const int i = c * CH + ii;
                const float dr = SDR[i];
                const float4 ds =
                    *reinterpret_cast<const float4*>(SDS + ii * DSP + (m << 2));
                float h0 = fmaxf(dr + ds.x, 0.f);
                float h1 = fmaxf(dr + ds.y, 0.f);
                float h2 = fmaxf(dr + ds.z, 0.f);
                float h3 = fmaxf(dr + ds.w, 0.f);
                unsigned long long hh0 = pk2(h0, h0), hh1 = pk2(h1, h1);
                unsigned long long hh2 = pk2(h2, h2), hh3 = pk2(h3, h3);

                const ulonglong2* wrow =
                    reinterpret_cast<const ulonglong2*>(SW2 + i * H2 + (n << 4));
                ulonglong2 p0 = wrow[0], p1 = wrow[1], p2 = wrow[2], p3 = wrow[3];
                unsigned long long B[8] = {p0.x, p0.y, p1.x, p1.y,
                                           p2.x, p2.y, p3.x, p3.y};
                #pragma unroll
                for (int q = 0; q < 8; q++) {
                    fma2(acc[q],      hh0, B[q]);
                    fma2(acc[8 + q],  hh1, B[q]);
                    fma2(acc[16 + q], hh2, B[q]);
                    fma2(acc[24 + q], hh3, B[q]);
                }
            }
        }
    }

    // ---- layer 3 partials (per thread: its 16 o's, its 4 edges) ----
    float part[4][DE];
    #pragma unroll
    for (int e = 0; e < 4; e++)
        #pragma unroll
        for (int k = 0; k < DE; k++) part[e][k] = 0.f;

    if (active) {
        #pragma unroll
        for (int e = 0; e < 4; e++) {
            #pragma unroll
            for (int q = 0; q < 8; q++) {
                float2 f = upk2(acc[e * 8 + q]);
                float a0 = fmaxf(f.x, 0.f);
                float a1 = fmaxf(f.y, 0.f);
                const int o0 = (n << 4) + 2 * q;
                #pragma unroll
                for (int k = 0; k < DE; k++)
                    part[e][k] = fmaf(a0, SW3[o0 * DE + k],
                                 fmaf(a1, SW3[(o0 + 1) * DE + k], part[e][k]));
            }
        }
    }

    // ---- reduce across the 4 output-groups (adjacent lanes) via shfl ----
    // then bias+relu on n==0 lanes, mask s==r, sum over this thread's 4 edges
    float ebar[DE];
    #pragma unroll
    for (int k = 0; k < DE; k++) {
        float s = 0.f;
        #pragma unroll
        for (int e = 0; e < 4; e++) {
            float v = part[e][k];
            v += __shfl_down_sync(0xffffffffu, v, 1);
            v += __shfl_down_sync(0xffffffffu, v, 2);
            if (n == 0) {
                float Ev = fmaxf(SB3[k] + v, 0.f);
                if ((m << 2) + e != r && active) s += Ev;
            }
        }
        ebar[k] = s;  // valid on n==0 lanes
    }
    // reduce the 8 quad-leader lanes (0,4,...,28) of each warp
    #pragma unroll
    for (int k = 0; k < DE; k++) {
        float v = ebar[k];
        v += __shfl_down_sync(0xffffffffu, v, 4);
        v += __shfl_down_sync(0xffffffffu, v, 8);
        v += __shfl_down_sync(0xffffffffu, v, 16);
        if (lane == 0) SRED[w * DE + k] = v;
    }
    __syncthreads();
    if (tid < DE) {
        float e = 0.f;
        #pragma unroll
        for (int ww = 0; ww < 6; ww++) e += SRED[ww * DE + tid];
        SEBAR[tid] = e;
    }
    __syncthreads();

    // ---- fused object MLP for node (b, r) ----
    if (tid < HID) {
        float a = fo1_b[tid];
        #pragma unroll
        for (int mm = 0; mm < PF; mm++)
            a = fmaf(SXR[mm], fo1_w[mm * HID + tid], a);
        #pragma unroll
        for (int mm = 0; mm < DE; mm++)
            a = fmaf(SEBAR[mm], fo1_w[(PF + mm) * HID + tid], a);
        SH1[tid] = fmaxf(a, 0.f);
    }
    __syncthreads();
    if (tid < H2) {
        float a = fo2_b[tid];
        #pragma unroll 8
        for (int mm = 0; mm < HID; mm++)
            a = fmaf(SH1[mm], fo2_w[mm * H2 + tid], a);
        SH2v[tid] = fmaxf(a, 0.f);
    }
    __syncthreads();
    if (tid < DOUT) {
        float a = fo3_b[tid];
        #pragma unroll
        for (int mm = 0; mm < H2; mm++)
            a = fmaf(SH2v[mm], fo3_w[mm * DOUT + tid], a);
        g_O[((size_t)b * NC + r) * DOUT + tid] = fmaxf(a, 0.f);
    }
}

// ============================================================================
// Kernel B: FC head. One block per batch, 512 threads, split-K reductions.
// ============================================================================
#define FCT 512
__global__ void __launch_bounds__(FCT) fc_kernel(
    const float* __restrict__ fc1_w, const float* __restrict__ fc1_b,
    const float* __restrict__ fc2_w, const float* __restrict__ fc2_b,
    const float* __restrict__ fc3_w, const float* __restrict__ fc3_b,
    float* __restrict__ out)
{
    __shared__ float sO[NC * DOUT];
    __shared__ float sp1[4][HID];
    __shared__ float sh1[HID];
    __shared__ float sp2[8][H2];
    __shared__ float sh2[H2];
    const int b = blockIdx.x, tid = threadIdx.x;

    for (int idx = tid; idx < NC * DOUT; idx += FCT)
        sO[idx] = g_O[(size_t)b * NC * DOUT + idx];
    __syncthreads();

    {
        const int o = tid & (HID - 1), p = tid >> 7;
        const int m0 = p * 282;
        float a = (p == 0) ? fc1_b[o] : 0.f;
        #pragma unroll 6
        for (int m = m0; m < m0 + 282; m++)
            a = fmaf(sO[m], fc1_w[m * HID + o], a);
        sp1[p][o] = a;
    }
    __syncthreads();
    if (tid < HID) {
        float h = sp1[0][tid] + sp1[1][tid] + sp1[2][tid] + sp1[3][tid];
        sh1[tid] = fmaxf(h, 0.f);
    }
    __syncthreads();

    {
        const int o = tid & (H2 - 1), p = tid >> 6;
        const int m0 = p * 16;
        float a = (p == 0) ? fc2_b[o] : 0.f;
        #pragma unroll
        for (int m = m0; m < m0 + 16; m++)
            a = fmaf(sh1[m], fc2_w[m * H2 + o], a);
        sp2[p][o] = a;
    }
    __syncthreads();
    if (tid < H2) {
        float h = 0.f;
        #pragma unroll
        for (int p = 0; p < 8; p++) h += sp2[p][tid];
        sh2[tid] = fmaxf(h, 0.f);
    }
    __syncthreads();

    if (tid < NT) {
        float a = fc3_b[tid];
        #pragma unroll
        for (int m = 0; m < H2; m++)
            a = fmaf(sh2[m], fc3_w[m * NT + tid], a);
        out[b * NT + tid] = a;
    }
}

// ============================================================================
// Launch
// ============================================================================
extern "C" void kernel_launch(void* const* d_in, const int* in_sizes, int n_in,
                              void* d_out, int out_size) {
    const float* x     = (const float*)d_in[0];
    const float* fr1_w = (const float*)d_in[1];
    const float* fr1_b = (const float*)d_in[2];
    const float* fr2_w = (const float*)d_in[3];
    const float* fr2_b = (const float*)d_in[4];
    const float* fr3_w = (const float*)d_in[5];
    const float* fr3_b = (const float*)d_in[6];
    const float* fo1_w = (const float*)d_in[7];
    const float* fo1_b = (const float*)d_in[8];
    const float* fo2_w = (const float*)d_in[9];
    const float* fo2_b = (const float*)d_in[10];
    const float* fo3_w = (const float*)d_in[11];
    const float* fo3_b = (const float*)d_in[12];
    const float* fc1_w = (const float*)d_in[13];
    const float* fc1_b = (const float*)d_in[14];
    const float* fc2_w = (const float*)d_in[15];
    const float* fc2_b = (const float*)d_in[16];
    const float* fc3_w = (const float*)d_in[17];
    const float* fc3_b = (const float*)d_in[18];
    float* out = (float*)d_out;

    dim3 pgrid(NC, BATCH);
    precompute_kernel<<<pgrid, HID>>>(x, fr1_w, fr1_b);

    dim3 grid(NC, BATCH);
    edge_obj_kernel<<<grid, TPB>>>(x,
                                   fr2_w, fr2_b, fr3_w, fr3_b,
                                   fo1_w, fo1_b, fo2_w, fo2_b, fo3_w, fo3_b);
    fc_kernel<<<BATCH, FCT>>>(fc1_w, fc1_b, fc2_w, fc2_b, fc3_w, fc3_b, out);
}

// round 5
// speedup vs baseline: 1.2428x; 1.2428x over previous
#include <cuda_runtime.h>
#include <cuda_bf16.h>
#include <cstdint>

// Problem constants
#define NC    188
#define PF    16
#define HID   128
#define H2    64
#define DE    5
#define DOUT  6
#define NT    5
#define BATCH 32
#define TPB   192   // 6 warps; 12 m16 tiles of the 192-row A

// A tile: 192 rows x 136 cols (128 + 4-u32 pad for conflict-free frags), bf16
#define SA_U32  68          // row stride in uint32 units (136 bf16)
#define A_BYTES 52224       // 192 * 68 * 4
#define B_BYTES 17408       // 64 * 68 * 4
#define SM_AHI  0
#define SM_ALO  52224
#define SM_BHI  104448
#define SM_BLO  121856
#define DYN_SMEM 139264

// Scratch
__device__ float g_O[BATCH * NC * DOUT];
__device__ float g_DR[BATCH * NC * HID];   // b1 + xr.W1r   [b][n][i]
__device__ float g_DSn[BATCH * NC * HID];  // xs.W1s        [b][n][i]
__device__ __align__(16) __nv_bfloat16 g_W2hi[H2 * 136];  // W2^T hi, row-major padded
__device__ __align__(16) __nv_bfloat16 g_W2lo[H2 * 136];  // W2^T lo

// pack two f32 -> bf16x2 {lo=a, hi=b}
#define CVT2(res, a, b) \
    asm("cvt.rn.bf16x2.f32 %0, %1, %2;" : "=r"(res) : "f"(b), "f"(a))

__device__ __forceinline__ void mma_bf16(float* d, const uint32_t* a,
                                         uint32_t b0, uint32_t b1) {
    asm volatile(
        "mma.sync.aligned.m16n8k16.row.col.f32.bf16.bf16.f32 "
        "{%0,%1,%2,%3}, {%4,%5,%6,%7}, {%8,%9}, {%0,%1,%2,%3};"
        : "+f"(d[0]), "+f"(d[1]), "+f"(d[2]), "+f"(d[3])
        : "r"(a[0]), "r"(a[1]), "r"(a[2]), "r"(a[3]), "r"(b0), "r"(b1));
}

// ============================================================================
// Kernel P: per-node layer-1 half-dots (f32)
// ============================================================================
__global__ void __launch_bounds__(HID) precompute_kernel(
    const float* __restrict__ x,
    const float* __restrict__ fr1_w, const float* __restrict__ fr1_b)
{
    __shared__ float SX[PF];
    const int n = blockIdx.x, b = blockIdx.y, i = threadIdx.x;
    if (i < PF) SX[i] = x[((size_t)b * NC + n) * PF + i];
    __syncthreads();
    float dr = fr1_b[i], ds = 0.f;
    #pragma unroll
    for (int m = 0; m < PF; m++) {
        float xm = SX[m];
        dr = fmaf(xm, fr1_w[m * HID + i], dr);
        ds = fmaf(xm, fr1_w[(PF + m) * HID + i], ds);
    }
    g_DR[((size_t)b * NC + n) * HID + i] = dr;
    g_DSn[((size_t)b * NC + n) * HID + i] = ds;
}

// ============================================================================
// Kernel W: split W2^T into bf16 hi/lo images [64][136] (row-major, padded)
// ============================================================================
__global__ void __launch_bounds__(256) w2prep_kernel(const float* __restrict__ fr2_w)
{
    int idx = blockIdx.x * 256 + threadIdx.x;
    if (idx < HID * H2) {
        int o = idx >> 7, k = idx & 127;           // o = n (0..63), k = 0..127
        float w = fr2_w[k * H2 + o];
        __nv_bfloat16 hi = __float2bfloat16(w);
        float hif = __bfloat162float(hi);
        __nv_bfloat16 lo = __float2bfloat16(w - hif);
        g_W2hi[o * 136 + k] = hi;
        g_W2lo[o * 136 + k] = lo;
    }
}

// ============================================================================
// Kernel A: one block per (receiver r, batch b).
// Layer-2 GEMM via mma.sync bf16 (3-term hi/lo split for fp32-grade accuracy).
// ============================================================================
__global__ void __launch_bounds__(TPB, 1) edge_obj_kernel(
    const float* __restrict__ x,
    const float* __restrict__ fr2_b,
    const float* __restrict__ fr3_w, const float* __restrict__ fr3_b,
    const float* __restrict__ fo1_w, const float* __restrict__ fo1_b,
    const float* __restrict__ fo2_w, const float* __restrict__ fo2_b,
    const float* __restrict__ fo3_w, const float* __restrict__ fo3_b)
{
    extern __shared__ __align__(16) unsigned char dsm[];
    __shared__ __align__(16) float SDR[HID];
    __shared__ __align__(16) float SW3p[H2 * 8];   // per o: w3[0..4], b2, 0, 0
    __shared__ float SB3[8];
    __shared__ float SXR[PF];
    __shared__ float SRED[6 * DE];
    __shared__ float SEBAR[8];
    __shared__ float SH1[HID];
    __shared__ float SH2v[H2];

    uint32_t* Ah = reinterpret_cast<uint32_t*>(dsm + SM_AHI);
    uint32_t* Al = reinterpret_cast<uint32_t*>(dsm + SM_ALO);
    uint32_t* Bh = reinterpret_cast<uint32_t*>(dsm + SM_BHI);
    uint32_t* Bl = reinterpret_cast<uint32_t*>(dsm + SM_BLO);
    float*    Dsm = reinterpret_cast<float*>(dsm + SM_AHI);  // reused after GEMM

    const int r = blockIdx.x, b = blockIdx.y;
    const int tid = threadIdx.x, wid = tid >> 5, lane = tid & 31;

    // ---- stage: W2 hi/lo (linear 16B copies), DR, SW3p, misc ----
    {
        const uint4* sh = reinterpret_cast<const uint4*>(g_W2hi);
        const uint4* sl = reinterpret_cast<const uint4*>(g_W2lo);
        uint4* dh = reinterpret_cast<uint4*>(Bh);
        uint4* dl = reinterpret_cast<uint4*>(Bl);
        #pragma unroll 2
        for (int idx = tid; idx < B_BYTES / 16; idx += TPB) {
            dh[idx] = sh[idx];
            dl[idx] = sl[idx];
        }
    }
    if (tid < HID) SDR[tid] = g_DR[((size_t)b * NC + r) * HID + tid];
    for (int idx = tid; idx < H2 * 8; idx += TPB) {
        int o = idx >> 3, k = idx & 7;
        SW3p[idx] = (k < 5) ? fr3_w[o * DE + k] : (k == 5 ? fr2_b[o] : 0.f);
    }
    if (tid < DE) SB3[tid] = fr3_b[tid];
    if (tid < PF) SXR[tid] = x[((size_t)b * NC + r) * PF + tid];
    __syncthreads();

    // ---- build H1 hi/lo: row s = tid, cols i: relu(DR[i] + DSn[s][i]) ----
    {
        const int row = tid;
        uint32_t* oh = Ah + row * SA_U32;
        uint32_t* ol = Al + row * SA_U32;
        if (row < NC) {
            const float4* dsn4 = reinterpret_cast<const float4*>(
                g_DSn + ((size_t)b * NC + row) * HID);
            const float4* drp4 = reinterpret_cast<const float4*>(SDR);
            #pragma unroll 8
            for (int g = 0; g < 32; g++) {
                float4 u = dsn4[g], p = drp4[g];
                float h0 = fmaxf(u.x + p.x, 0.f), h1 = fmaxf(u.y + p.y, 0.f);
                float h2 = fmaxf(u.z + p.z, 0.f), h3 = fmaxf(u.w + p.w, 0.f);
                uint32_t hi01, hi23, lo01, lo23;
                CVT2(hi01, h0, h1);
                CVT2(hi23, h2, h3);
                float f0 = __uint_as_float(hi01 << 16);
                float f1 = __uint_as_float(hi01 & 0xFFFF0000u);
                float f2 = __uint_as_float(hi23 << 16);
                float f3 = __uint_as_float(hi23 & 0xFFFF0000u);
                CVT2(lo01, h0 - f0, h1 - f1);
                CVT2(lo23, h2 - f2, h3 - f3);
                *reinterpret_cast<uint2*>(oh + 2 * g) = make_uint2(hi01, hi23);
                *reinterpret_cast<uint2*>(ol + 2 * g) = make_uint2(lo01, lo23);
            }
        } else {
            uint2 z = make_uint2(0u, 0u);
            #pragma unroll 8
            for (int g = 0; g < 32; g++) {
                *reinterpret_cast<uint2*>(oh + 2 * g) = z;
                *reinterpret_cast<uint2*>(ol + 2 * g) = z;
            }
        }
    }
    __syncthreads();

    // ---- warp GEMM: warp wid handles rows [32*wid, 32*wid+32) ----
    const int mbase = wid * 32;
    const int gid = lane >> 2, tig = lane & 3;
    float d[2][8][4];
    #pragma unroll
    for (int mt = 0; mt < 2; mt++)
        #pragma unroll
        for (int nt = 0; nt < 8; nt++)
            #pragma unroll
            for (int e = 0; e < 4; e++) d[mt][nt][e] = 0.f;

    #pragma unroll
    for (int kt = 0; kt < 8; kt++) {
        const int kb2 = (kt * 16 + tig * 2) >> 1;   // u32 col index
        // A fragments (hi & lo) for both m-tiles
        uint32_t ah[2][4], al[2][4];
        #pragma unroll
        for (int mt = 0; mt < 2; mt++) {
            const int base = (mbase + mt * 16 + gid) * SA_U32 + kb2;
            ah[mt][0] = Ah[base];
            ah[mt][1] = Ah[base + 8 * SA_U32];
            ah[mt][2] = Ah[base + 4];
            ah[mt][3] = Ah[base + 8 * SA_U32 + 4];
            al[mt][0] = Al[base];
            al[mt][1] = Al[base + 8 * SA_U32];
            al[mt][2] = Al[base + 4];
            al[mt][3] = Al[base + 8 * SA_U32 + 4];
        }
        // B fragments (hi & lo) for all 8 n-tiles
        uint32_t bh[8][2], bl[8][2];
        #pragma unroll
        for (int nt = 0; nt < 8; nt++) {
            const int bi = (nt * 8 + gid) * SA_U32 + kb2;
            bh[nt][0] = Bh[bi];
            bh[nt][1] = Bh[bi + 4];
            bl[nt][0] = Bl[bi];
            bl[nt][1] = Bl[bi + 4];
        }
        // 3 passes of 16 independent HMMAs (hi*hi, lo*hi, hi*lo)
        #pragma unroll
        for (int nt = 0; nt < 8; nt++) {
            mma_bf16(d[0][nt], ah[0], bh[nt][0], bh[nt][1]);
            mma_bf16(d[1][nt], ah[1], bh[nt][0], bh[nt][1]);
        }
        #pragma unroll
        for (int nt = 0; nt < 8; nt++) {
            mma_bf16(d[0][nt], al[0], bh[nt][0], bh[nt][1]);
            mma_bf16(d[1][nt], al[1], bh[nt][0], bh[nt][1]);
        }
        #pragma unroll
        for (int nt = 0; nt < 8; nt++) {
            mma_bf16(d[0][nt], ah[0], bl[nt][0], bl[nt][1]);
            mma_bf16(d[1][nt], ah[1], bl[nt][0], bl[nt][1]);
        }
    }
    __syncthreads();   // all warps done reading A smem

    // ---- store D fragments to smem (reuse A_hi region), stride 68 f32 ----
    #pragma unroll
    for (int mt = 0; mt < 2; mt++) {
        const int row0 = mbase + mt * 16 + gid;
        #pragma unroll
        for (int nt = 0; nt < 8; nt++) {
            const int col = nt * 8 + tig * 2;
            *reinterpret_cast<float2*>(Dsm + row0 * SA_U32 + col) =
                make_float2(d[mt][nt][0], d[mt][nt][1]);
            *reinterpret_cast<float2*>(Dsm + (row0 + 8) * SA_U32 + col) =
                make_float2(d[mt][nt][2], d[mt][nt][3]);
        }
    }
    __syncthreads();

    // ---- per-row epilogue: h2 = relu(D + b2); E = relu(b3 + h2 @ W3) ----
    float Ek[DE] = {0.f, 0.f, 0.f, 0.f, 0.f};
    const bool valid = (tid < NC) && (tid != r);
    if (valid) {
        float a0 = 0.f, a1 = 0.f, a2 = 0.f, a3 = 0.f, a4 = 0.f;
        const float4* D4 = reinterpret_cast<const float4*>(Dsm + tid * SA_U32);
        #pragma unroll 4
        for (int j = 0; j < 16; j++) {
            float4 dv = D4[j];
            #pragma unroll
            for (int e = 0; e < 4; e++) {
                const int o = 4 * j + e;
                float4 wA = *reinterpret_cast<const float4*>(SW3p + o * 8);
                float4 wB = *reinterpret_cast<const float4*>(SW3p + o * 8 + 4);
                float dvv = (e == 0) ? dv.x : (e == 1) ? dv.y : (e == 2) ? dv.z : dv.w;
                float hv = fmaxf(dvv + wB.y, 0.f);
                a0 = fmaf(hv, wA.x, a0);
                a1 = fmaf(hv, wA.y, a1);
                a2 = fmaf(hv, wA.z, a2);
                a3 = fmaf(hv, wA.w, a3);
                a4 = fmaf(hv, wB.x, a4);
            }
        }
        Ek[0] = fmaxf(SB3[0] + a0, 0.f);
        Ek[1] = fmaxf(SB3[1] + a1, 0.f);
        Ek[2] = fmaxf(SB3[2] + a2, 0.f);
        Ek[3] = fmaxf(SB3[3] + a3, 0.f);
        Ek[4] = fmaxf(SB3[4] + a4, 0.f);
    }

    // ---- deterministic reduction over senders ----
    #pragma unroll
    for (int k = 0; k < DE; k++) {
        float v = Ek[k];
        #pragma unroll
        for (int off = 16; off > 0; off >>= 1)
            v += __shfl_down_sync(0xffffffffu, v, off);
        if (lane == 0) SRED[wid * DE + k] = v;
    }
    __syncthreads();
    if (tid < DE) {
        float e = 0.f;
        #pragma unroll
        for (int w = 0; w < 6; w++) e += SRED[w * DE + tid];
        SEBAR[tid] = e;
    }
    __syncthreads();

    // ---- fused object MLP for node (b, r) ----
    if (tid < HID) {
        float a = fo1_b[tid];
        #pragma unroll
        for (int m = 0; m < PF; m++)
            a = fmaf(SXR[m], fo1_w[m * HID + tid], a);
        #pragma unroll
        for (int m = 0; m < DE; m++)
            a = fmaf(SEBAR[m], fo1_w[(PF + m) * HID + tid], a);
        SH1[tid] = fmaxf(a, 0.f);
    }
    __syncthreads();
    if (tid < H2) {
        float a = fo2_b[tid];
        #pragma unroll 8
        for (int m = 0; m < HID; m++)
            a = fmaf(SH1[m], fo2_w[m * H2 + tid], a);
        SH2v[tid] = fmaxf(a, 0.f);
    }
    __syncthreads();
    if (tid < DOUT) {
        float a = fo3_b[tid];
        #pragma unroll
        for (int m = 0; m < H2; m++)
            a = fmaf(SH2v[m], fo3_w[m * DOUT + tid], a);
        g_O[((size_t)b * NC + r) * DOUT + tid] = fmaxf(a, 0.f);
    }
}

// ============================================================================
// Kernel B: FC head (split-K, one block per batch)
// ============================================================================
#define FCT 512
__global__ void __launch_bounds__(FCT) fc_kernel(
    const float* __restrict__ fc1_w, const float* __restrict__ fc1_b,
    const float* __restrict__ fc2_w, const float* __restrict__ fc2_b,
    const float* __restrict__ fc3_w, const float* __restrict__ fc3_b,
    float* __restrict__ out)
{
    __shared__ float sO[NC * DOUT];
    __shared__ float sp1[4][HID];
    __shared__ float sh1[HID];
    __shared__ float sp2[8][H2];
    __shared__ float sh2[H2];
    const int b = blockIdx.x, tid = threadIdx.x;

    for (int idx = tid; idx < NC * DOUT; idx += FCT)
        sO[idx] = g_O[(size_t)b * NC * DOUT + idx];
    __syncthreads();

    {
        const int o = tid & (HID - 1), p = tid >> 7;
        const int m0 = p * 282;
        float a = (p == 0) ? fc1_b[o] : 0.f;
        #pragma unroll 6
        for (int m = m0; m < m0 + 282; m++)
            a = fmaf(sO[m], fc1_w[m * HID + o], a);
        sp1[p][o] = a;
    }
    __syncthreads();
    if (tid < HID)
        sh1[tid] = fmaxf(sp1[0][tid] + sp1[1][tid] + sp1[2][tid] + sp1[3][tid], 0.f);
    __syncthreads();

    {
        const int o = tid & (H2 - 1), p = tid >> 6;
        const int m0 = p * 16;
        float a = (p == 0) ? fc2_b[o] : 0.f;
        #pragma unroll
        for (int m = m0; m < m0 + 16; m++)
            a = fmaf(sh1[m], fc2_w[m * H2 + o], a);
        sp2[p][o] = a;
    }
    __syncthreads();
    if (tid < H2) {
        float h = 0.f;
        #pragma unroll
        for (int p = 0; p < 8; p++) h += sp2[p][tid];
        sh2[tid] = fmaxf(h, 0.f);
    }
    __syncthreads();

    if (tid < NT) {
        float a = fc3_b[tid];
        #pragma unroll
        for (int m = 0; m < H2; m++)
            a = fmaf(sh2[m], fc3_w[m * NT + tid], a);
        out[b * NT + tid] = a;
    }
}

// ============================================================================
// Launch
// ============================================================================
extern "C" void kernel_launch(void* const* d_in, const int* in_sizes, int n_in,
                              void* d_out, int out_size) {
    const float* x     = (const float*)d_in[0];
    const float* fr1_w = (const float*)d_in[1];
    const float* fr1_b = (const float*)d_in[2];
    const float* fr2_w = (const float*)d_in[3];
    const float* fr2_b = (const float*)d_in[4];
    const float* fr3_w = (const float*)d_in[5];
    const float* fr3_b = (const float*)d_in[6];
    const float* fo1_w = (const float*)d_in[7];
    const float* fo1_b = (const float*)d_in[8];
    const float* fo2_w = (const float*)d_in[9];
    const float* fo2_b = (const float*)d_in[10];
    const float* fo3_w = (const float*)d_in[11];
    const float* fo3_b = (const float*)d_in[12];
    const float* fc1_w = (const float*)d_in[13];
    const float* fc1_b = (const float*)d_in[14];
    const float* fc2_w = (const float*)d_in[15];
    const float* fc2_b = (const float*)d_in[16];
    const float* fc3_w = (const float*)d_in[17];
    const float* fc3_b = (const float*)d_in[18];
    float* out = (float*)d_out;

    static bool attr_set = false;
    if (!attr_set) {
        cudaFuncSetAttribute(edge_obj_kernel,
                             cudaFuncAttributeMaxDynamicSharedMemorySize, DYN_SMEM);
        attr_set = true;
    }

    dim3 pgrid(NC, BATCH);
    precompute_kernel<<<pgrid, HID>>>(x, fr1_w, fr1_b);
    w2prep_kernel<<<32, 256>>>(fr2_w);

    dim3 grid(NC, BATCH);
    edge_obj_kernel<<<grid, TPB, DYN_SMEM>>>(x, fr2_b, fr3_w, fr3_b,
                                             fo1_w, fo1_b, fo2_w, fo2_b,
                                             fo3_w, fo3_b);
    fc_kernel<<<BATCH, FCT>>>(fc1_w, fc1_b, fc2_w, fc2_b, fc3_w, fc3_b, out);
}

// round 6
// speedup vs baseline: 1.2900x; 1.0380x over previous
#include <cuda_runtime.h>
#include <cuda_bf16.h>
#include <cstdint>

// Problem constants
#define NC    188
#define PF    16
#define HID   128
#define H2    64
#define DE    5
#define DOUT  6
#define NT    5
#define BATCH 32
#define TPB   384   // 12 warps; one m16 tile per warp (192 rows)

// A tile: 192 rows x 136 cols bf16 (stride 68 u32, pad for conflict-free frags)
#define SA_U32  68
#define A_BYTES 52224       // 192 * 68 * 4
#define B_BYTES 17408       // 64 * 68 * 4
#define SM_A    0
#define SM_BHI  52224
#define SM_BLO  69632
#define DYN_SMEM 87040      // fits 2 blocks/SM (174KB of 228KB)

// Scratch
__device__ float g_O[BATCH * NC * DOUT];
__device__ float g_DR[BATCH * NC * HID];   // b1 + xr.W1r   [b][n][i]
__device__ float g_DSn[BATCH * NC * HID];  // xs.W1s        [b][n][i]
__device__ __align__(16) __nv_bfloat16 g_W2hi[H2 * 136];
__device__ __align__(16) __nv_bfloat16 g_W2lo[H2 * 136];

// pack two f32 -> bf16x2 {lo=a, hi=b}
#define CVT2(res, a, b) \
    asm("cvt.rn.bf16x2.f32 %0, %1, %2;" : "=r"(res) : "f"(b), "f"(a))

__device__ __forceinline__ void mma_bf16(float* d, const uint32_t* a,
                                         uint32_t b0, uint32_t b1) {
    asm volatile(
        "mma.sync.aligned.m16n8k16.row.col.f32.bf16.bf16.f32 "
        "{%0,%1,%2,%3}, {%4,%5,%6,%7}, {%8,%9}, {%0,%1,%2,%3};"
        : "+f"(d[0]), "+f"(d[1]), "+f"(d[2]), "+f"(d[3])
        : "r"(a[0]), "r"(a[1]), "r"(a[2]), "r"(a[3]), "r"(b0), "r"(b1));
}

// ============================================================================
// Kernel P: per-node layer-1 half-dots (f32)
// ============================================================================
__global__ void __launch_bounds__(HID) precompute_kernel(
    const float* __restrict__ x,
    const float* __restrict__ fr1_w, const float* __restrict__ fr1_b)
{
    __shared__ float SX[PF];
    const int n = blockIdx.x, b = blockIdx.y, i = threadIdx.x;
    if (i < PF) SX[i] = x[((size_t)b * NC + n) * PF + i];
    __syncthreads();
    float dr = fr1_b[i], ds = 0.f;
    #pragma unroll
    for (int m = 0; m < PF; m++) {
        float xm = SX[m];
        dr = fmaf(xm, fr1_w[m * HID + i], dr);
        ds = fmaf(xm, fr1_w[(PF + m) * HID + i], ds);
    }
    g_DR[((size_t)b * NC + n) * HID + i] = dr;
    g_DSn[((size_t)b * NC + n) * HID + i] = ds;
}

// ============================================================================
// Kernel W: split W2^T into bf16 hi/lo images [64][136]
// ============================================================================
__global__ void __launch_bounds__(256) w2prep_kernel(const float* __restrict__ fr2_w)
{
    int idx = blockIdx.x * 256 + threadIdx.x;
    if (idx < HID * H2) {
        int o = idx >> 7, k = idx & 127;
        float w = fr2_w[k * H2 + o];
        __nv_bfloat16 hi = __float2bfloat16(w);
        float hif = __bfloat162float(hi);
        __nv_bfloat16 lo = __float2bfloat16(w - hif);
        g_W2hi[o * 136 + k] = hi;
        g_W2lo[o * 136 + k] = lo;
    }
}

// ============================================================================
// Kernel A: one block per (receiver r, batch b). mma.sync bf16 3-term split,
// A buffer rebuilt (hi -> lo) between passes to halve smem -> occupancy 2.
// ============================================================================
__global__ void __launch_bounds__(TPB, 2) edge_obj_kernel(
    const float* __restrict__ x,
    const float* __restrict__ fr2_b,
    const float* __restrict__ fr3_w, const float* __restrict__ fr3_b,
    const float* __restrict__ fo1_w, const float* __restrict__ fo1_b,
    const float* __restrict__ fo2_w, const float* __restrict__ fo2_b,
    const float* __restrict__ fo3_w, const float* __restrict__ fo3_b)
{
    extern __shared__ __align__(16) unsigned char dsm[];
    __shared__ __align__(16) float SDR[HID];
    __shared__ __align__(16) float SW3p[H2 * 8];   // per o: w3[0..4], b2, 0, 0
    __shared__ float SB3[8];
    __shared__ float SXR[PF];
    __shared__ float SRED[12 * DE];
    __shared__ float SEBAR[8];
    __shared__ float SH1[HID];
    __shared__ float SH2v[H2];

    uint32_t* Abuf = reinterpret_cast<uint32_t*>(dsm + SM_A);
    uint32_t* Bh = reinterpret_cast<uint32_t*>(dsm + SM_BHI);
    uint32_t* Bl = reinterpret_cast<uint32_t*>(dsm + SM_BLO);

    const int r = blockIdx.x, b = blockIdx.y;
    const int tid = threadIdx.x, wid = tid >> 5, lane = tid & 31;
    const int gid = lane >> 2, tig = lane & 3;

    // ---- stage small operands + B hi/lo ----
    {
        const uint4* sh = reinterpret_cast<const uint4*>(g_W2hi);
        const uint4* sl = reinterpret_cast<const uint4*>(g_W2lo);
        uint4* dh = reinterpret_cast<uint4*>(Bh);
        uint4* dl = reinterpret_cast<uint4*>(Bl);
        for (int idx = tid; idx < B_BYTES / 16; idx += TPB) {
            dh[idx] = sh[idx];
            dl[idx] = sl[idx];
        }
    }
    if (tid < HID) SDR[tid] = g_DR[((size_t)b * NC + r) * HID + tid];
    for (int idx = tid; idx < H2 * 8; idx += TPB) {
        int o = idx >> 3, k = idx & 7;
        SW3p[idx] = (k < 5) ? fr3_w[o * DE + k] : (k == 5 ? fr2_b[o] : 0.f);
    }
    if (tid < DE) SB3[tid] = fr3_b[tid];
    if (tid < PF) SXR[tid] = x[((size_t)b * NC + r) * PF + tid];
    __syncthreads();

    // ---- build A pass (mode 0: hi, mode 1: lo). row = tid>>1, half = tid&1 ----
    const int arow = tid >> 1, ahalf = tid & 1;
    const float4* dsn4 = (arow < NC)
        ? reinterpret_cast<const float4*>(g_DSn + ((size_t)b * NC + arow) * HID)
          + ahalf * 16
        : nullptr;
    const float4* drp4 = reinterpret_cast<const float4*>(SDR) + ahalf * 16;
    uint32_t* aout = Abuf + arow * SA_U32 + ahalf * 32;

    #define BUILD_A(MODE)                                                      \
    do {                                                                       \
        if (arow < NC) {                                                       \
            _Pragma("unroll 4")                                                \
            for (int g = 0; g < 16; g++) {                                     \
                float4 u = dsn4[g], p = drp4[g];                               \
                float h0 = fmaxf(u.x + p.x, 0.f), h1 = fmaxf(u.y + p.y, 0.f);  \
                float h2 = fmaxf(u.z + p.z, 0.f), h3 = fmaxf(u.w + p.w, 0.f);  \
                uint32_t hi01, hi23;                                           \
                CVT2(hi01, h0, h1);                                            \
                CVT2(hi23, h2, h3);                                            \
                uint32_t o01 = hi01, o23 = hi23;                               \
                if (MODE) {                                                    \
                    float f0 = __uint_as_float(hi01 << 16);                    \
                    float f1 = __uint_as_float(hi01 & 0xFFFF0000u);            \
                    float f2 = __uint_as_float(hi23 << 16);                    \
                    float f3 = __uint_as_float(hi23 & 0xFFFF0000u);            \
                    CVT2(o01, h0 - f0, h1 - f1);                               \
                    CVT2(o23, h2 - f2, h3 - f3);                               \
                }                                                              \
                *reinterpret_cast<uint2*>(aout + 2 * g) = make_uint2(o01, o23);\
            }                                                                  \
        } else {                                                               \
            uint2 z = make_uint2(0u, 0u);                                      \
            _Pragma("unroll 4")                                                \
            for (int g = 0; g < 16; g++)                                       \
                *reinterpret_cast<uint2*>(aout + 2 * g) = z;                   \
        }                                                                      \
    } while (0)

    BUILD_A(0);
    __syncthreads();

    // ---- GEMM: warp wid owns m16 tile rows [16*wid, 16*wid+16) ----
    float d[8][4];
    #pragma unroll
    for (int nt = 0; nt < 8; nt++)
        #pragma unroll
        for (int e = 0; e < 4; e++) d[nt][e] = 0.f;

    const int abase0 = (wid * 16 + gid) * SA_U32;

    // Phase 1: A=hi vs B hi and B lo
    #pragma unroll
    for (int kt = 0; kt < 8; kt++) {
        const int kb = kt * 8 + tig;
        uint32_t af[4];
        af[0] = Abuf[abase0 + kb];
        af[1] = Abuf[abase0 + 8 * SA_U32 + kb];
        af[2] = Abuf[abase0 + kb + 4];
        af[3] = Abuf[abase0 + 8 * SA_U32 + kb + 4];
        #pragma unroll
        for (int nt = 0; nt < 8; nt++) {
            const int bi = (nt * 8 + gid) * SA_U32 + kb;
            mma_bf16(d[nt], af, Bh[bi], Bh[bi + 4]);
            mma_bf16(d[nt], af, Bl[bi], Bl[bi + 4]);
        }
    }
    __syncthreads();   // all warps done reading A(hi)

    BUILD_A(1);        // rebuild A as lo
    __syncthreads();

    // Phase 2: A=lo vs B hi
    #pragma unroll
    for (int kt = 0; kt < 8; kt++) {
        const int kb = kt * 8 + tig;
        uint32_t af[4];
        af[0] = Abuf[abase0 + kb];
        af[1] = Abuf[abase0 + 8 * SA_U32 + kb];
        af[2] = Abuf[abase0 + kb + 4];
        af[3] = Abuf[abase0 + 8 * SA_U32 + kb + 4];
        #pragma unroll
        for (int nt = 0; nt < 8; nt++) {
            const int bi = (nt * 8 + gid) * SA_U32 + kb;
            mma_bf16(d[nt], af, Bh[bi], Bh[bi + 4]);
        }
    }

    // ---- fragment-direct epilogue ----
    // Thread covers rows {16*wid+gid, +8}, o in {8nt+2tig, 8nt+2tig+1}.
    float p0[DE] = {0.f, 0.f, 0.f, 0.f, 0.f};
    float p1[DE] = {0.f, 0.f, 0.f, 0.f, 0.f};
    #pragma unroll
    for (int nt = 0; nt < 8; nt++) {
        const int c = nt * 8 + tig * 2;
        float4 wA0 = *reinterpret_cast<const float4*>(SW3p + c * 8);
        float4 wB0 = *reinterpret_cast<const float4*>(SW3p + c * 8 + 4);
        float4 wA1 = *reinterpret_cast<const float4*>(SW3p + (c + 1) * 8);
        float4 wB1 = *reinterpret_cast<const float4*>(SW3p + (c + 1) * 8 + 4);
        float h00 = fmaxf(d[nt][0] + wB0.y, 0.f);   // row0, o=c
        float h01 = fmaxf(d[nt][1] + wB1.y, 0.f);   // row0, o=c+1
        float h10 = fmaxf(d[nt][2] + wB0.y, 0.f);   // row1, o=c
        float h11 = fmaxf(d[nt][3] + wB1.y, 0.f);   // row1, o=c+1
        p0[0] = fmaf(h00, wA0.x, fmaf(h01, wA1.x, p0[0]));
        p0[1] = fmaf(h00, wA0.y, fmaf(h01, wA1.y, p0[1]));
        p0[2] = fmaf(h00, wA0.z, fmaf(h01, wA1.z, p0[2]));
        p0[3] = fmaf(h00, wA0.w, fmaf(h01, wA1.w, p0[3]));
        p0[4] = fmaf(h00, wB0.x, fmaf(h01, wB1.x, p0[4]));
        p1[0] = fmaf(h10, wA0.x, fmaf(h11, wA1.x, p1[0]));
        p1[1] = fmaf(h10, wA0.y, fmaf(h11, wA1.y, p1[1]));
        p1[2] = fmaf(h10, wA0.z, fmaf(h11, wA1.z, p1[2]));
        p1[3] = fmaf(h10, wA0.w, fmaf(h11, wA1.w, p1[3]));
        p1[4] = fmaf(h10, wB0.x, fmaf(h11, wB1.x, p1[4]));
    }
    // reduce across the 4 tig lanes of each quad (all lanes get the sum)
    const int row0 = wid * 16 + gid, row1 = row0 + 8;
    const bool v0 = (row0 < NC) && (row0 != r);
    const bool v1 = (row1 < NC) && (row1 != r);
    #pragma unroll
    for (int k = 0; k < DE; k++) {
        float a = p0[k], c = p1[k];
        a += __shfl_xor_sync(0xffffffffu, a, 1);
        a += __shfl_xor_sync(0xffffffffu, a, 2);
        c += __shfl_xor_sync(0xffffffffu, c, 1);
        c += __shfl_xor_sync(0xffffffffu, c, 2);
        float e = (v0 ? fmaxf(SB3[k] + a, 0.f) : 0.f)
                + (v1 ? fmaxf(SB3[k] + c, 0.f) : 0.f);
        // sum over the 8 quads (values replicated within each quad)
        e += __shfl_down_sync(0xffffffffu, e, 16);
        e += __shfl_down_sync(0xffffffffu, e, 8);
        e += __shfl_down_sync(0xffffffffu, e, 4);
        if (lane == 0) SRED[wid * DE + k] = e;
    }
    __syncthreads();
    if (tid < DE) {
        float e = 0.f;
        #pragma unroll
        for (int w = 0; w < 12; w++) e += SRED[w * DE + tid];
        SEBAR[tid] = e;
    }
    __syncthreads();

    // ---- fused object MLP for node (b, r) ----
    if (tid < HID) {
        float a = fo1_b[tid];
        #pragma unroll
        for (int m = 0; m < PF; m++)
            a = fmaf(SXR[m], fo1_w[m * HID + tid], a);
        #pragma unroll
        for (int m = 0; m < DE; m++)
            a = fmaf(SEBAR[m], fo1_w[(PF + m) * HID + tid], a);
        SH1[tid] = fmaxf(a, 0.f);
    }
    __syncthreads();
    if (tid < H2) {
        float a = fo2_b[tid];
        #pragma unroll 8
        for (int m = 0; m < HID; m++)
            a = fmaf(SH1[m], fo2_w[m * H2 + tid], a);
        SH2v[tid] = fmaxf(a, 0.f);
    }
    __syncthreads();
    if (tid < DOUT) {
        float a = fo3_b[tid];
        #pragma unroll
        for (int m = 0; m < H2; m++)
            a = fmaf(SH2v[m], fo3_w[m * DOUT + tid], a);
        g_O[((size_t)b * NC + r) * DOUT + tid] = fmaxf(a, 0.f);
    }
}

// ============================================================================
// Kernel B: FC head. One block per batch, 1024 threads, split-K.
// ============================================================================
#define FCT 1024
__global__ void __launch_bounds__(FCT) fc_kernel(
    const float* __restrict__ fc1_w, const float* __restrict__ fc1_b,
    const float* __restrict__ fc2_w, const float* __restrict__ fc2_b,
    const float* __restrict__ fc3_w, const float* __restrict__ fc3_b,
    float* __restrict__ out)
{
    __shared__ float sO[NC * DOUT];
    __shared__ float sp1[8][HID];
    __shared__ float sh1[HID];
    __shared__ float sp2[16][H2];
    __shared__ float sh2[H2];
    const int b = blockIdx.x, tid = threadIdx.x;

    for (int idx = tid; idx < NC * DOUT; idx += FCT)
        sO[idx] = g_O[(size_t)b * NC * DOUT + idx];
    __syncthreads();

    // fc1: 1128 -> 128, 8-way split over K (141 each)
    {
        const int o = tid & (HID - 1), p = tid >> 7;
        const int m0 = p * 141;
        float a = (p == 0) ? fc1_b[o] : 0.f;
        #pragma unroll 3
        for (int m = m0; m < m0 + 141; m++)
            a = fmaf(sO[m], fc1_w[m * HID + o], a);
        sp1[p][o] = a;
    }
    __syncthreads();
    if (tid < HID) {
        float h = 0.f;
        #pragma unroll
        for (int p = 0; p < 8; p++) h += sp1[p][tid];
        sh1[tid] = fmaxf(h, 0.f);
    }
    __syncthreads();

    // fc2: 128 -> 64, 16-way split over K (8 each)
    {
        const int o = tid & (H2 - 1), p = tid >> 6;
        const int m0 = p * 8;
        float a = (p == 0) ? fc2_b[o] : 0.f;
        #pragma unroll
        for (int m = m0; m < m0 + 8; m++)
            a = fmaf(sh1[m], fc2_w[m * H2 + o], a);
        sp2[p][o] = a;
    }
    __syncthreads();
    if (tid < H2) {
        float h = 0.f;
        #pragma unroll
        for (int p = 0; p < 16; p++) h += sp2[p][tid];
        sh2[tid] = fmaxf(h, 0.f);
    }
    __syncthreads();

    if (tid < NT) {
        float a = fc3_b[tid];
        #pragma unroll
        for (int m = 0; m < H2; m++)
            a = fmaf(sh2[m], fc3_w[m * NT + tid], a);
        out[b * NT + tid] = a;
    }
}

// ============================================================================
// Launch
// ============================================================================
extern "C" void kernel_launch(void* const* d_in, const int* in_sizes, int n_in,
                              void* d_out, int out_size) {
    const float* x     = (const float*)d_in[0];
    const float* fr1_w = (const float*)d_in[1];
    const float* fr1_b = (const float*)d_in[2];
    const float* fr2_w = (const float*)d_in[3];
    const float* fr2_b = (const float*)d_in[4];
    const float* fr3_w = (const float*)d_in[5];
    const float* fr3_b = (const float*)d_in[6];
    const float* fo1_w = (const float*)d_in[7];
    const float* fo1_b = (const float*)d_in[8];
    const float* fo2_w = (const float*)d_in[9];
    const float* fo2_b = (const float*)d_in[10];
    const float* fo3_w = (const float*)d_in[11];
    const float* fo3_b = (const float*)d_in[12];
    const float* fc1_w = (const float*)d_in[13];
    const float* fc1_b = (const float*)d_in[14];
    const float* fc2_w = (const float*)d_in[15];
    const float* fc2_b = (const float*)d_in[16];
    const float* fc3_w = (const float*)d_in[17];
    const float* fc3_b = (const float*)d_in[18];
    float* out = (float*)d_out;

    static bool attr_set = false;
    if (!attr_set) {
        cudaFuncSetAttribute(edge_obj_kernel,
                             cudaFuncAttributeMaxDynamicSharedMemorySize, DYN_SMEM);
        attr_set = true;
    }

    dim3 pgrid(NC, BATCH);
    precompute_kernel<<<pgrid, HID>>>(x, fr1_w, fr1_b);
    w2prep_kernel<<<32, 256>>>(fr2_w);

    dim3 grid(NC, BATCH);
    edge_obj_kernel<<<grid, TPB, DYN_SMEM>>>(x, fr2_b, fr3_w, fr3_b,
                                             fo1_w, fo1_b, fo2_w, fo2_b,
                                             fo3_w, fo3_b);
    fc_kernel<<<BATCH, FCT>>>(fc1_w, fc1_b, fc2_w, fc2_b, fc3_w, fc3_b, out);
}

// round 7
// speedup vs baseline: 2.0308x; 1.5742x over previous
#include <cuda_runtime.h>
#include <cuda_bf16.h>
#include <cuda_fp16.h>
#include <cstdint>

// Problem constants
#define NC    188
#define PF    16
#define HID   128
#define H2    64
#define DE    5
#define DOUT  6
#define NT    5
#define BATCH 32
#define TPB   384   // 12 warps; one m16 tile per warp (192 rows)

// A tile: 192 rows x 136 cols fp16 (stride 68 u32, pad for conflict-free frags)
#define SA_U32  68
#define A_BYTES 52224       // 192 * 68 * 4
#define B_BYTES 17408       // 64 * 68 * 4
#define SM_A    0
#define SM_B    52224
#define DYN_SMEM 69632      // 2 blocks/SM comfortably

// Scratch
__device__ float g_O[BATCH * NC * DOUT];
__device__ float g_DR[BATCH * NC * HID];   // b1 + xr.W1r   [b][n][i]
__device__ float g_DSn[BATCH * NC * HID];  // xs.W1s        [b][n][i]
__device__ __align__(16) __half g_W2h[H2 * 136];  // W2^T fp16, row-major padded
__device__ float g_P1[BATCH * 8 * HID];    // fc1 split-K partials

// pack two f32 -> f16x2 {lo=a, hi=b}
#define CVT2H(res, a, b) \
    asm("cvt.rn.f16x2.f32 %0, %1, %2;" : "=r"(res) : "f"(b), "f"(a))

__device__ __forceinline__ void mma_f16(float* d, const uint32_t* a,
                                        uint32_t b0, uint32_t b1) {
    asm volatile(
        "mma.sync.aligned.m16n8k16.row.col.f32.f16.f16.f32 "
        "{%0,%1,%2,%3}, {%4,%5,%6,%7}, {%8,%9}, {%0,%1,%2,%3};"
        : "+f"(d[0]), "+f"(d[1]), "+f"(d[2]), "+f"(d[3])
        : "r"(a[0]), "r"(a[1]), "r"(a[2]), "r"(a[3]), "r"(b0), "r"(b1));
}

// ============================================================================
// Kernel P: per-node layer-1 half-dots (f32)
// ============================================================================
__global__ void __launch_bounds__(HID) precompute_kernel(
    const float* __restrict__ x,
    const float* __restrict__ fr1_w, const float* __restrict__ fr1_b)
{
    __shared__ float SX[PF];
    const int n = blockIdx.x, b = blockIdx.y, i = threadIdx.x;
    if (i < PF) SX[i] = x[((size_t)b * NC + n) * PF + i];
    __syncthreads();
    float dr = fr1_b[i], ds = 0.f;
    #pragma unroll
    for (int m = 0; m < PF; m++) {
        float xm = SX[m];
        dr = fmaf(xm, fr1_w[m * HID + i], dr);
        ds = fmaf(xm, fr1_w[(PF + m) * HID + i], ds);
    }
    g_DR[((size_t)b * NC + n) * HID + i] = dr;
    g_DSn[((size_t)b * NC + n) * HID + i] = ds;
}

// ============================================================================
// Kernel W: W2^T as fp16 image [64][136]
// ============================================================================
__global__ void __launch_bounds__(256) w2prep_kernel(const float* __restrict__ fr2_w)
{
    int idx = blockIdx.x * 256 + threadIdx.x;
    if (idx < HID * H2) {
        int o = idx >> 7, k = idx & 127;
        g_W2h[o * 136 + k] = __float2half_rn(fr2_w[k * H2 + o]);
    }
}

// ============================================================================
// Kernel A: one block per (receiver r, batch b). Single-pass fp16 mma.sync.
// ============================================================================
__global__ void __launch_bounds__(TPB, 2) edge_obj_kernel(
    const float* __restrict__ x,
    const float* __restrict__ fr2_b,
    const float* __restrict__ fr3_w, const float* __restrict__ fr3_b,
    const float* __restrict__ fo1_w, const float* __restrict__ fo1_b,
    const float* __restrict__ fo2_w, const float* __restrict__ fo2_b,
    const float* __restrict__ fo3_w, const float* __restrict__ fo3_b)
{
    extern __shared__ __align__(16) unsigned char dsm[];
    __shared__ __align__(16) float SDR[HID];
    __shared__ __align__(16) float SW3p[H2 * 8];   // per o: w3[0..4], b2, 0, 0
    __shared__ float SB3[8];
    __shared__ float SXR[PF];
    __shared__ float SRED[12 * DE];
    __shared__ float SEBAR[8];
    __shared__ float SH1[HID];
    __shared__ float SH2v[H2];

    uint32_t* Abuf = reinterpret_cast<uint32_t*>(dsm + SM_A);
    uint32_t* Bh = reinterpret_cast<uint32_t*>(dsm + SM_B);

    const int r = blockIdx.x, b = blockIdx.y;
    const int tid = threadIdx.x, wid = tid >> 5, lane = tid & 31;
    const int gid = lane >> 2, tig = lane & 3;

    // ---- stage small operands + B ----
    {
        const uint4* sh = reinterpret_cast<const uint4*>(g_W2h);
        uint4* dh = reinterpret_cast<uint4*>(Bh);
        for (int idx = tid; idx < B_BYTES / 16; idx += TPB) dh[idx] = sh[idx];
    }
    if (tid < HID) SDR[tid] = g_DR[((size_t)b * NC + r) * HID + tid];
    for (int idx = tid; idx < H2 * 8; idx += TPB) {
        int o = idx >> 3, k = idx & 7;
        SW3p[idx] = (k < 5) ? fr3_w[o * DE + k] : (k == 5 ? fr2_b[o] : 0.f);
    }
    if (tid < DE) SB3[tid] = fr3_b[tid];
    if (tid < PF) SXR[tid] = x[((size_t)b * NC + r) * PF + tid];
    __syncthreads();

    // ---- build A (fp16): row = tid>>1, half = tid&1 (64 floats each) ----
    {
        const int arow = tid >> 1, ahalf = tid & 1;
        uint32_t* aout = Abuf + arow * SA_U32 + ahalf * 32;
        if (arow < NC) {
            const float4* dsn4 = reinterpret_cast<const float4*>(
                g_DSn + ((size_t)b * NC + arow) * HID) + ahalf * 16;
            const float4* drp4 = reinterpret_cast<const float4*>(SDR) + ahalf * 16;
            #pragma unroll 4
            for (int g = 0; g < 16; g++) {
                float4 u = dsn4[g], p = drp4[g];
                float h0 = fmaxf(u.x + p.x, 0.f), h1 = fmaxf(u.y + p.y, 0.f);
                float h2 = fmaxf(u.z + p.z, 0.f), h3 = fmaxf(u.w + p.w, 0.f);
                uint32_t o01, o23;
                CVT2H(o01, h0, h1);
                CVT2H(o23, h2, h3);
                *reinterpret_cast<uint2*>(aout + 2 * g) = make_uint2(o01, o23);
            }
        } else {
            uint2 z = make_uint2(0u, 0u);
            #pragma unroll 4
            for (int g = 0; g < 16; g++)
                *reinterpret_cast<uint2*>(aout + 2 * g) = z;
        }
    }
    __syncthreads();

    // ---- GEMM: warp wid owns m16 tile rows [16*wid, 16*wid+16) ----
    float d[8][4];
    #pragma unroll
    for (int nt = 0; nt < 8; nt++)
        #pragma unroll
        for (int e = 0; e < 4; e++) d[nt][e] = 0.f;

    const int abase0 = (wid * 16 + gid) * SA_U32;
    #pragma unroll
    for (int kt = 0; kt < 8; kt++) {
        const int kb = kt * 8 + tig;
        uint32_t af[4];
        af[0] = Abuf[abase0 + kb];
        af[1] = Abuf[abase0 + 8 * SA_U32 + kb];
        af[2] = Abuf[abase0 + kb + 4];
        af[3] = Abuf[abase0 + 8 * SA_U32 + kb + 4];
        #pragma unroll
        for (int nt = 0; nt < 8; nt++) {
            const int bi = (nt * 8 + gid) * SA_U32 + kb;
            mma_f16(d[nt], af, Bh[bi], Bh[bi + 4]);
        }
    }

    // ---- fragment-direct epilogue ----
    // Thread covers rows {16*wid+gid, +8}, o in {8nt+2tig, 8nt+2tig+1}.
    float p0[DE] = {0.f, 0.f, 0.f, 0.f, 0.f};
    float p1[DE] = {0.f, 0.f, 0.f, 0.f, 0.f};
    #pragma unroll
    for (int nt = 0; nt < 8; nt++) {
        const int c = nt * 8 + tig * 2;
        float4 wA0 = *reinterpret_cast<const float4*>(SW3p + c * 8);
        float4 wB0 = *reinterpret_cast<const float4*>(SW3p + c * 8 + 4);
        float4 wA1 = *reinterpret_cast<const float4*>(SW3p + (c + 1) * 8);
        float4 wB1 = *reinterpret_cast<const float4*>(SW3p + (c + 1) * 8 + 4);
        float h00 = fmaxf(d[nt][0] + wB0.y, 0.f);
        float h01 = fmaxf(d[nt][1] + wB1.y, 0.f);
        float h10 = fmaxf(d[nt][2] + wB0.y, 0.f);
        float h11 = fmaxf(d[nt][3] + wB1.y, 0.f);
        p0[0] = fmaf(h00, wA0.x, fmaf(h01, wA1.x, p0[0]));
        p0[1] = fmaf(h00, wA0.y, fmaf(h01, wA1.y, p0[1]));
        p0[2] = fmaf(h00, wA0.z, fmaf(h01, wA1.z, p0[2]));
        p0[3] = fmaf(h00, wA0.w, fmaf(h01, wA1.w, p0[3]));
        p0[4] = fmaf(h00, wB0.x, fmaf(h01, wB1.x, p0[4]));
        p1[0] = fmaf(h10, wA0.x, fmaf(h11, wA1.x, p1[0]));
        p1[1] = fmaf(h10, wA0.y, fmaf(h11, wA1.y, p1[1]));
        p1[2] = fmaf(h10, wA0.z, fmaf(h11, wA1.z, p1[2]));
        p1[3] = fmaf(h10, wA0.w, fmaf(h11, wA1.w, p1[3]));
        p1[4] = fmaf(h10, wB0.x, fmaf(h11, wB1.x, p1[4]));
    }
    const int row0 = wid * 16 + gid, row1 = row0 + 8;
    const bool v0 = (row0 < NC) && (row0 != r);
    const bool v1 = (row1 < NC) && (row1 != r);
    #pragma unroll
    for (int k = 0; k < DE; k++) {
        float a = p0[k], c = p1[k];
        a += __shfl_xor_sync(0xffffffffu, a, 1);
        a += __shfl_xor_sync(0xffffffffu, a, 2);
        c += __shfl_xor_sync(0xffffffffu, c, 1);
        c += __shfl_xor_sync(0xffffffffu, c, 2);
        float e = (v0 ? fmaxf(SB3[k] + a, 0.f) : 0.f)
                + (v1 ? fmaxf(SB3[k] + c, 0.f) : 0.f);
        e += __shfl_down_sync(0xffffffffu, e, 16);
        e += __shfl_down_sync(0xffffffffu, e, 8);
        e += __shfl_down_sync(0xffffffffu, e, 4);
        if (lane == 0) SRED[wid * DE + k] = e;
    }
    __syncthreads();
    if (tid < DE) {
        float e = 0.f;
        #pragma unroll
        for (int w = 0; w < 12; w++) e += SRED[w * DE + tid];
        SEBAR[tid] = e;
    }
    __syncthreads();

    // ---- fused object MLP for node (b, r) ----
    if (tid < HID) {
        float a = fo1_b[tid];
        #pragma unroll
        for (int m = 0; m < PF; m++)
            a = fmaf(SXR[m], fo1_w[m * HID + tid], a);
        #pragma unroll
        for (int m = 0; m < DE; m++)
            a = fmaf(SEBAR[m], fo1_w[(PF + m) * HID + tid], a);
        SH1[tid] = fmaxf(a, 0.f);
    }
    __syncthreads();
    if (tid < H2) {
        float a = fo2_b[tid];
        #pragma unroll 8
        for (int m = 0; m < HID; m++)
            a = fmaf(SH1[m], fo2_w[m * H2 + tid], a);
        SH2v[tid] = fmaxf(a, 0.f);
    }
    __syncthreads();
    if (tid < DOUT) {
        float a = fo3_b[tid];
        #pragma unroll
        for (int m = 0; m < H2; m++)
            a = fmaf(SH2v[m], fo3_w[m * DOUT + tid], a);
        g_O[((size_t)b * NC + r) * DOUT + tid] = fmaxf(a, 0.f);
    }
}

// ============================================================================
// Kernel B1: fc1 split-K partials. grid (BATCH, 8), 256 threads.
// ============================================================================
__global__ void __launch_bounds__(256) fc1_kernel(
    const float* __restrict__ fc1_w, const float* __restrict__ fc1_b)
{
    __shared__ float sp[2][HID];
    const int b = blockIdx.x, p = blockIdx.y;
    const int o = threadIdx.x & (HID - 1), h = threadIdx.x >> 7;
    const int m0 = p * 141 + h * 71;
    const int mend = p * 141 + (h ? 141 : 71);
    const float* Ob = g_O + (size_t)b * NC * DOUT;
    float a = (p == 0 && h == 0) ? fc1_b[o] : 0.f;
    #pragma unroll 4
    for (int m = m0; m < mend; m++)
        a = fmaf(Ob[m], fc1_w[m * HID + o], a);
    sp[h][o] = a;
    __syncthreads();
    if (threadIdx.x < HID)
        g_P1[((size_t)b * 8 + p) * HID + threadIdx.x] =
            sp[0][threadIdx.x] + sp[1][threadIdx.x];
}

// ============================================================================
// Kernel B2: finish head. grid BATCH, 128 threads.
// ============================================================================
__global__ void __launch_bounds__(HID) fc2_kernel(
    const float* __restrict__ fc2_w, const float* __restrict__ fc2_b,
    const float* __restrict__ fc3_w, const float* __restrict__ fc3_b,
    float* __restrict__ out)
{
    __shared__ float sh1[HID];
    __shared__ float sp2[2][H2];
    __shared__ float sh2[H2];
    const int b = blockIdx.x, tid = threadIdx.x;

    float a = 0.f;
    #pragma unroll
    for (int p = 0; p < 8; p++)
        a += g_P1[((size_t)b * 8 + p) * HID + tid];
    sh1[tid] = fmaxf(a, 0.f);
    __syncthreads();

    {
        const int o = tid & (H2 - 1), pp = tid >> 6;
        const int m0 = pp * 64;
        float a2 = (pp == 0) ? fc2_b[o] : 0.f;
        #pragma unroll 4
        for (int m = m0; m < m0 + 64; m++)
            a2 = fmaf(sh1[m], fc2_w[m * H2 + o], a2);
        sp2[pp][o] = a2;
    }
    __syncthreads();
    if (tid < H2) sh2[tid] = fmaxf(sp2[0][tid] + sp2[1][tid], 0.f);
    __syncthreads();

    if (tid < NT) {
        float a3 = fc3_b[tid];
        #pragma unroll
        for (int m = 0; m < H2; m++)
            a3 = fmaf(sh2[m], fc3_w[m * NT + tid], a3);
        out[b * NT + tid] = a3;
    }
}

// ============================================================================
// Launch
// ============================================================================
extern "C" void kernel_launch(void* const* d_in, const int* in_sizes, int n_in,
                              void* d_out, int out_size) {
    const float* x     = (const float*)d_in[0];
    const float* fr1_w = (const float*)d_in[1];
    const float* fr1_b = (const float*)d_in[2];
    const float* fr2_w = (const float*)d_in[3];
    const float* fr2_b = (const float*)d_in[4];
    const float* fr3_w = (const float*)d_in[5];
    const float* fr3_b = (const float*)d_in[6];
    const float* fo1_w = (const float*)d_in[7];
    const float* fo1_b = (const float*)d_in[8];
    const float* fo2_w = (const float*)d_in[9];
    const float* fo2_b = (const float*)d_in[10];
    const float* fo3_w = (const float*)d_in[11];
    const float* fo3_b = (const float*)d_in[12];
    const float* fc1_w = (const float*)d_in[13];
    const float* fc1_b = (const float*)d_in[14];
    const float* fc2_w = (const float*)d_in[15];
    const float* fc2_b = (const float*)d_in[16];
    const float* fc3_w = (const float*)d_in[17];
    const float* fc3_b = (const float*)d_in[18];
    float* out = (float*)d_out;

    static bool attr_set = false;
    if (!attr_set) {
        cudaFuncSetAttribute(edge_obj_kernel,
                             cudaFuncAttributeMaxDynamicSharedMemorySize, DYN_SMEM);
        attr_set = true;
    }

    dim3 pgrid(NC, BATCH);
    precompute_kernel<<<pgrid, HID>>>(x, fr1_w, fr1_b);
    w2prep_kernel<<<32, 256>>>(fr2_w);

    dim3 grid(NC, BATCH);
    edge_obj_kernel<<<grid, TPB, DYN_SMEM>>>(x, fr2_b, fr3_w, fr3_b,
                                             fo1_w, fo1_b, fo2_w, fo2_b,
                                             fo3_w, fo3_b);
    dim3 fgrid(BATCH, 8);
    fc1_kernel<<<fgrid, 256>>>(fc1_w, fc1_b);
    fc2_kernel<<<BATCH, HID>>>(fc2_w, fc2_b, fc3_w, fc3_b, out);
}

// round 8
// speedup vs baseline: 2.3838x; 1.1738x over previous
#include <cuda_runtime.h>
#include <cuda_bf16.h>
#include <cuda_fp16.h>
#include <cstdint>

// Problem constants
#define NC    188
#define PF    16
#define HID   128
#define H2    64
#define DE    5
#define DOUT  6
#define NT    5
#define BATCH 32
#define TPB   384   // 12 warps; one m16 tile per warp (192 rows)

// A tile: 192 rows x 136 cols fp16 (stride 68 u32, pad for conflict-free frags)
#define SA_U32  68
#define A_BYTES 52224
#define B_BYTES 17408
#define SM_A    0
#define SM_B    52224
#define DYN_SMEM 69632      // 2 blocks/SM

// Scratch
__device__ float g_O[BATCH * NC * DOUT];
__device__ float g_Ebar[BATCH * NC * DE];
__device__ float g_DR[BATCH * NC * HID];   // b1 + xr.W1r   [b][n][i]
__device__ float g_DSn[BATCH * NC * HID];  // xs.W1s        [b][n][i]
__device__ __align__(16) __half g_W2h[H2 * 136];
__device__ float g_P1[BATCH * 16 * HID];   // fc1 split-K partials

// pack two f32 -> f16x2 {lo=a, hi=b}
#define CVT2H(res, a, b) \
    asm("cvt.rn.f16x2.f32 %0, %1, %2;" : "=r"(res) : "f"(b), "f"(a))

__device__ __forceinline__ void mma_f16(float* d, const uint32_t* a,
                                        uint32_t b0, uint32_t b1) {
    asm volatile(
        "mma.sync.aligned.m16n8k16.row.col.f32.f16.f16.f32 "
        "{%0,%1,%2,%3}, {%4,%5,%6,%7}, {%8,%9}, {%0,%1,%2,%3};"
        : "+f"(d[0]), "+f"(d[1]), "+f"(d[2]), "+f"(d[3])
        : "r"(a[0]), "r"(a[1]), "r"(a[2]), "r"(a[3]), "r"(b0), "r"(b1));
}

// ============================================================================
// Kernel P: per-node layer-1 half-dots (f32)
// ============================================================================
__global__ void __launch_bounds__(HID) precompute_kernel(
    const float* __restrict__ x,
    const float* __restrict__ fr1_w, const float* __restrict__ fr1_b)
{
    __shared__ float SX[PF];
    const int n = blockIdx.x, b = blockIdx.y, i = threadIdx.x;
    if (i < PF) SX[i] = x[((size_t)b * NC + n) * PF + i];
    __syncthreads();
    float dr = fr1_b[i], ds = 0.f;
    #pragma unroll
    for (int m = 0; m < PF; m++) {
        float xm = SX[m];
        dr = fmaf(xm, fr1_w[m * HID + i], dr);
        ds = fmaf(xm, fr1_w[(PF + m) * HID + i], ds);
    }
    g_DR[((size_t)b * NC + n) * HID + i] = dr;
    g_DSn[((size_t)b * NC + n) * HID + i] = ds;
}

// ============================================================================
// Kernel W: W2^T as fp16 image [64][136]
// ============================================================================
__global__ void __launch_bounds__(256) w2prep_kernel(const float* __restrict__ fr2_w)
{
    int idx = blockIdx.x * 256 + threadIdx.x;
    if (idx < HID * H2) {
        int o = idx >> 7, k = idx & 127;
        g_W2h[o * 136 + k] = __float2half_rn(fr2_w[k * H2 + o]);
    }
}

// ============================================================================
// Kernel A: one block per (receiver r, batch b). fp16 mma.sync -> Ebar only.
// ============================================================================
__global__ void __launch_bounds__(TPB, 2) edge_kernel(
    const float* __restrict__ fr2_b,
    const float* __restrict__ fr3_w, const float* __restrict__ fr3_b)
{
    extern __shared__ __align__(16) unsigned char dsm[];
    __shared__ __align__(16) float SDR[HID];
    __shared__ __align__(16) float SW3p[H2 * 8];   // per o: w3[0..4], b2, 0, 0
    __shared__ float SB3[8];
    __shared__ float SRED[12 * DE];

    uint32_t* Abuf = reinterpret_cast<uint32_t*>(dsm + SM_A);
    uint32_t* Bh = reinterpret_cast<uint32_t*>(dsm + SM_B);

    const int r = blockIdx.x, b = blockIdx.y;
    const int tid = threadIdx.x, wid = tid >> 5, lane = tid & 31;
    const int gid = lane >> 2, tig = lane & 3;

    // ---- stage small operands + B ----
    {
        const uint4* sh = reinterpret_cast<const uint4*>(g_W2h);
        uint4* dh = reinterpret_cast<uint4*>(Bh);
        for (int idx = tid; idx < B_BYTES / 16; idx += TPB) dh[idx] = sh[idx];
    }
    if (tid < HID) SDR[tid] = g_DR[((size_t)b * NC + r) * HID + tid];
    for (int idx = tid; idx < H2 * 8; idx += TPB) {
        int o = idx >> 3, k = idx & 7;
        SW3p[idx] = (k < 5) ? fr3_w[o * DE + k] : (k == 5 ? fr2_b[o] : 0.f);
    }
    if (tid < DE) SB3[tid] = fr3_b[tid];
    __syncthreads();

    // ---- build A (fp16): row = tid>>1, half = tid&1 (64 floats each) ----
    {
        const int arow = tid >> 1, ahalf = tid & 1;
        uint32_t* aout = Abuf + arow * SA_U32 + ahalf * 32;
        if (arow < NC) {
            const float4* dsn4 = reinterpret_cast<const float4*>(
                g_DSn + ((size_t)b * NC + arow) * HID) + ahalf * 16;
            const float4* drp4 = reinterpret_cast<const float4*>(SDR) + ahalf * 16;
            #pragma unroll 4
            for (int g = 0; g < 16; g++) {
                float4 u = dsn4[g], p = drp4[g];
                float h0 = fmaxf(u.x + p.x, 0.f), h1 = fmaxf(u.y + p.y, 0.f);
                float h2 = fmaxf(u.z + p.z, 0.f), h3 = fmaxf(u.w + p.w, 0.f);
                uint32_t o01, o23;
                CVT2H(o01, h0, h1);
                CVT2H(o23, h2, h3);
                *reinterpret_cast<uint2*>(aout + 2 * g) = make_uint2(o01, o23);
            }
        } else {
            uint2 z = make_uint2(0u, 0u);
            #pragma unroll 4
            for (int g = 0; g < 16; g++)
                *reinterpret_cast<uint2*>(aout + 2 * g) = z;
        }
    }
    __syncthreads();

    // ---- GEMM: warp wid owns m16 tile rows [16*wid, 16*wid+16) ----
    float d[8][4];
    #pragma unroll
    for (int nt = 0; nt < 8; nt++)
        #pragma unroll
        for (int e = 0; e < 4; e++) d[nt][e] = 0.f;

    const int abase0 = (wid * 16 + gid) * SA_U32;
    #pragma unroll
    for (int kt = 0; kt < 8; kt++) {
        const int kb = kt * 8 + tig;
        uint32_t af[4];
        af[0] = Abuf[abase0 + kb];
        af[1] = Abuf[abase0 + 8 * SA_U32 + kb];
        af[2] = Abuf[abase0 + kb + 4];
        af[3] = Abuf[abase0 + 8 * SA_U32 + kb + 4];
        #pragma unroll
        for (int nt = 0; nt < 8; nt++) {
            const int bi = (nt * 8 + gid) * SA_U32 + kb;
            mma_f16(d[nt], af, Bh[bi], Bh[bi + 4]);
        }
    }

    // ---- fragment-direct epilogue: layer 3 partials ----
    float p0[DE] = {0.f, 0.f, 0.f, 0.f, 0.f};
    float p1[DE] = {0.f, 0.f, 0.f, 0.f, 0.f};
    #pragma unroll
    for (int nt = 0; nt < 8; nt++) {
        const int c = nt * 8 + tig * 2;
        float4 wA0 = *reinterpret_cast<const float4*>(SW3p + c * 8);
        float4 wB0 = *reinterpret_cast<const float4*>(SW3p + c * 8 + 4);
        float4 wA1 = *reinterpret_cast<const float4*>(SW3p + (c + 1) * 8);
        float4 wB1 = *reinterpret_cast<const float4*>(SW3p + (c + 1) * 8 + 4);
        float h00 = fmaxf(d[nt][0] + wB0.y, 0.f);
        float h01 = fmaxf(d[nt][1] + wB1.y, 0.f);
        float h10 = fmaxf(d[nt][2] + wB0.y, 0.f);
        float h11 = fmaxf(d[nt][3] + wB1.y, 0.f);
        p0[0] = fmaf(h00, wA0.x, fmaf(h01, wA1.x, p0[0]));
        p0[1] = fmaf(h00, wA0.y, fmaf(h01, wA1.y, p0[1]));
        p0[2] = fmaf(h00, wA0.z, fmaf(h01, wA1.z, p0[2]));
        p0[3] = fmaf(h00, wA0.w, fmaf(h01, wA1.w, p0[3]));
        p0[4] = fmaf(h00, wB0.x, fmaf(h01, wB1.x, p0[4]));
        p1[0] = fmaf(h10, wA0.x, fmaf(h11, wA1.x, p1[0]));
        p1[1] = fmaf(h10, wA0.y, fmaf(h11, wA1.y, p1[1]));
        p1[2] = fmaf(h10, wA0.z, fmaf(h11, wA1.z, p1[2]));
        p1[3] = fmaf(h10, wA0.w, fmaf(h11, wA1.w, p1[3]));
        p1[4] = fmaf(h10, wB0.x, fmaf(h11, wB1.x, p1[4]));
    }
    const int row0 = wid * 16 + gid, row1 = row0 + 8;
    const bool v0 = (row0 < NC) && (row0 != r);
    const bool v1 = (row1 < NC) && (row1 != r);
    #pragma unroll
    for (int k = 0; k < DE; k++) {
        float a = p0[k], c = p1[k];
        a += __shfl_xor_sync(0xffffffffu, a, 1);
        a += __shfl_xor_sync(0xffffffffu, a, 2);
        c += __shfl_xor_sync(0xffffffffu, c, 1);
        c += __shfl_xor_sync(0xffffffffu, c, 2);
        float e = (v0 ? fmaxf(SB3[k] + a, 0.f) : 0.f)
                + (v1 ? fmaxf(SB3[k] + c, 0.f) : 0.f);
        e += __shfl_down_sync(0xffffffffu, e, 16);
        e += __shfl_down_sync(0xffffffffu, e, 8);
        e += __shfl_down_sync(0xffffffffu, e, 4);
        if (lane == 0) SRED[wid * DE + k] = e;
    }
    __syncthreads();
    if (tid < DE) {
        float e = 0.f;
        #pragma unroll
        for (int w = 0; w < 12; w++) e += SRED[w * DE + tid];
        g_Ebar[((size_t)b * NC + r) * DE + tid] = e;
    }
}

// ============================================================================
// Kernel O: object MLP per node. grid (NC, BATCH), 128 threads.
// ============================================================================
__global__ void __launch_bounds__(HID) obj_kernel(
    const float* __restrict__ x,
    const float* __restrict__ fo1_w, const float* __restrict__ fo1_b,
    const float* __restrict__ fo2_w, const float* __restrict__ fo2_b,
    const float* __restrict__ fo3_w, const float* __restrict__ fo3_b)
{
    __shared__ float SC[24];        // [x(16), Ebar(5)]
    __shared__ float SH1[HID];
    __shared__ float SP2[2][H2];
    __shared__ float SH2[H2];
    const int n = blockIdx.x, b = blockIdx.y, tid = threadIdx.x;

    if (tid < PF) SC[tid] = x[((size_t)b * NC + n) * PF + tid];
    if (tid >= 32 && tid < 32 + DE)
        SC[PF + tid - 32] = g_Ebar[((size_t)b * NC + n) * DE + (tid - 32)];
    __syncthreads();

    // fo1: 21 -> 128
    {
        float a = fo1_b[tid];
        #pragma unroll
        for (int m = 0; m < PF + DE; m++)
            a = fmaf(SC[m], fo1_w[m * HID + tid], a);
        SH1[tid] = fmaxf(a, 0.f);
    }
    __syncthreads();

    // fo2: 128 -> 64, 2-way split-K
    {
        const int o = tid & (H2 - 1), p = tid >> 6;
        float a = (p == 0) ? fo2_b[o] : 0.f;
        const int m0 = p * 64;
        #pragma unroll 8
        for (int m = m0; m < m0 + 64; m++)
            a = fmaf(SH1[m], fo2_w[m * H2 + o], a);
        SP2[p][o] = a;
    }
    __syncthreads();
    if (tid < H2) SH2[tid] = fmaxf(SP2[0][tid] + SP2[1][tid], 0.f);
    __syncthreads();

    // fo3: 64 -> 6
    if (tid < DOUT) {
        float a = fo3_b[tid];
        #pragma unroll
        for (int m = 0; m < H2; m++)
            a = fmaf(SH2[m], fo3_w[m * DOUT + tid], a);
        g_O[((size_t)b * NC + n) * DOUT + tid] = fmaxf(a, 0.f);
    }
}

// ============================================================================
// Kernel B1: fc1 split-K partials. grid (BATCH, 16), 128 threads.
// ============================================================================
__global__ void __launch_bounds__(HID) fc1_kernel(
    const float* __restrict__ fc1_w, const float* __restrict__ fc1_b)
{
    const int b = blockIdx.x, p = blockIdx.y, o = threadIdx.x;
    const int m0 = p * 71;
    const int mend = (m0 + 71 < NC * DOUT) ? m0 + 71 : NC * DOUT;
    const float* Ob = g_O + (size_t)b * NC * DOUT;
    float a = (p == 0) ? fc1_b[o] : 0.f;
    #pragma unroll 4
    for (int m = m0; m < mend; m++)
        a = fmaf(Ob[m], fc1_w[m * HID + o], a);
    g_P1[((size_t)b * 16 + p) * HID + o] = a;
}

// ============================================================================
// Kernel B2: finish head. grid BATCH, 128 threads.
// ============================================================================
__global__ void __launch_bounds__(HID) fc2_kernel(
    const float* __restrict__ fc2_w, const float* __restrict__ fc2_b,
    const float* __restrict__ fc3_w, const float* __restrict__ fc3_b,
    float* __restrict__ out)
{
    __shared__ float sh1[HID];
    __shared__ float sp2[2][H2];
    __shared__ float sh2[H2];
    const int b = blockIdx.x, tid = threadIdx.x;

    float a = 0.f;
    #pragma unroll
    for (int p = 0; p < 16; p++)
        a += g_P1[((size_t)b * 16 + p) * HID + tid];
    sh1[tid] = fmaxf(a, 0.f);
    __syncthreads();

    {
        const int o = tid & (H2 - 1), pp = tid >> 6;
        const int m0 = pp * 64;
        float a2 = (pp == 0) ? fc2_b[o] : 0.f;
        #pragma unroll 4
        for (int m = m0; m < m0 + 64; m++)
            a2 = fmaf(sh1[m], fc2_w[m * H2 + o], a2);
        sp2[pp][o] = a2;
    }
    __syncthreads();
    if (tid < H2) sh2[tid] = fmaxf(sp2[0][tid] + sp2[1][tid], 0.f);
    __syncthreads();

    if (tid < NT) {
        float a3 = fc3_b[tid];
        #pragma unroll
        for (int m = 0; m < H2; m++)
            a3 = fmaf(sh2[m], fc3_w[m * NT + tid], a3);
        out[b * NT + tid] = a3;
    }
}

// ============================================================================
// Launch
// ============================================================================
extern "C" void kernel_launch(void* const* d_in, const int* in_sizes, int n_in,
                              void* d_out, int out_size) {
    const float* x     = (const float*)d_in[0];
    const float* fr1_w = (const float*)d_in[1];
    const float* fr1_b = (const float*)d_in[2];
    const float* fr2_w = (const float*)d_in[3];
    const float* fr2_b = (const float*)d_in[4];
    const float* fr3_w = (const float*)d_in[5];
    const float* fr3_b = (const float*)d_in[6];
    const float* fo1_w = (const float*)d_in[7];
    const float* fo1_b = (const float*)d_in[8];
    const float* fo2_w = (const float*)d_in[9];
    const float* fo2_b = (const float*)d_in[10];
    const float* fo3_w = (const float*)d_in[11];
    const float* fo3_b = (const float*)d_in[12];
    const float* fc1_w = (const float*)d_in[13];
    const float* fc1_b = (const float*)d_in[14];
    const float* fc2_w = (const float*)d_in[15];
    const float* fc2_b = (const float*)d_in[16];
    const float* fc3_w = (const float*)d_in[17];
    const float* fc3_b = (const float*)d_in[18];
    float* out = (float*)d_out;

    static bool attr_set = false;
    if (!attr_set) {
        cudaFuncSetAttribute(edge_kernel,
                             cudaFuncAttributeMaxDynamicSharedMemorySize, DYN_SMEM);
        attr_set = true;
    }

    dim3 pgrid(NC, BATCH);
    precompute_kernel<<<pgrid, HID>>>(x, fr1_w, fr1_b);
    w2prep_kernel<<<32, 256>>>(fr2_w);

    dim3 grid(NC, BATCH);
    edge_kernel<<<grid, TPB, DYN_SMEM>>>(fr2_b, fr3_w, fr3_b);
    obj_kernel<<<grid, HID>>>(x, fo1_w, fo1_b, fo2_w, fo2_b, fo3_w, fo3_b);

    dim3 fgrid(BATCH, 16);
    fc1_kernel<<<fgrid, HID>>>(fc1_w, fc1_b);
    fc2_kernel<<<BATCH, HID>>>(fc2_w, fc2_b, fc3_w, fc3_b, out);
}

// round 9
// speedup vs baseline: 2.4615x; 1.0326x over previous
#include <cuda_runtime.h>
#include <cuda_bf16.h>
#include <cuda_fp16.h>
#include <cstdint>

// Problem constants
#define NC    188
#define PF    16
#define HID   128
#define H2    64
#define DE    5
#define DOUT  6
#define NT    5
#define BATCH 32
#define TPB   384   // 12 warps; one m16 tile per warp (192 rows)

// A tile: 192 rows x 136 cols fp16 (stride 68 u32, pad for conflict-free frags)
#define SA_U32  68
#define A_BYTES 52224
#define B_BYTES 17408
#define SM_A    0
#define SM_B    52224
#define DYN_SMEM 69632      // 3 blocks/SM: 208896 B of 228KB carveout

// Scratch
__device__ float g_O[BATCH * NC * DOUT];
__device__ float g_Ebar[BATCH * NC * DE];
__device__ float g_DR[BATCH * NC * HID];   // b1 + xr.W1r   [b][n][i]
__device__ float g_DSn[BATCH * NC * HID];  // xs.W1s        [b][n][i]
__device__ __align__(16) __half g_W2h[H2 * 136];
__device__ float g_P1[BATCH * 16 * HID];   // fc1 split-K partials

// pack two f32 -> f16x2 {lo=a, hi=b}
#define CVT2H(res, a, b) \
    asm("cvt.rn.f16x2.f32 %0, %1, %2;" : "=r"(res) : "f"(b), "f"(a))

__device__ __forceinline__ void mma_f16(float* d, const uint32_t* a,
                                        uint32_t b0, uint32_t b1) {
    asm volatile(
        "mma.sync.aligned.m16n8k16.row.col.f32.f16.f16.f32 "
        "{%0,%1,%2,%3}, {%4,%5,%6,%7}, {%8,%9}, {%0,%1,%2,%3};"
        : "+f"(d[0]), "+f"(d[1]), "+f"(d[2]), "+f"(d[3])
        : "r"(a[0]), "r"(a[1]), "r"(a[2]), "r"(a[3]), "r"(b0), "r"(b1));
}

// ============================================================================
// Kernel P: per-node layer-1 half-dots. 4 nodes/block, 512 threads.
// ============================================================================
__global__ void __launch_bounds__(512) precompute_kernel(
    const float* __restrict__ x,
    const float* __restrict__ fr1_w, const float* __restrict__ fr1_b)
{
    __shared__ float SX[4][PF];
    const int sub = threadIdx.x >> 7;            // node within block, 0..3
    const int i = threadIdx.x & (HID - 1);
    const int n = blockIdx.x * 4 + sub;          // 47*4 = 188 exactly
    const int b = blockIdx.y;
    if (i < PF) SX[sub][i] = x[((size_t)b * NC + n) * PF + i];
    __syncthreads();
    float dr = fr1_b[i], ds = 0.f;
    #pragma unroll
    for (int m = 0; m < PF; m++) {
        float xm = SX[sub][m];
        dr = fmaf(xm, fr1_w[m * HID + i], dr);
        ds = fmaf(xm, fr1_w[(PF + m) * HID + i], ds);
    }
    g_DR[((size_t)b * NC + n) * HID + i] = dr;
    g_DSn[((size_t)b * NC + n) * HID + i] = ds;
}

// ============================================================================
// Kernel W: W2^T as fp16 image [64][136]
// ============================================================================
__global__ void __launch_bounds__(256) w2prep_kernel(const float* __restrict__ fr2_w)
{
    int idx = blockIdx.x * 256 + threadIdx.x;
    if (idx < HID * H2) {
        int o = idx >> 7, k = idx & 127;
        g_W2h[o * 136 + k] = __float2half_rn(fr2_w[k * H2 + o]);
    }
}

// ============================================================================
// Kernel A: one block per (receiver r, batch b). fp16 mma.sync -> Ebar.
// Occupancy 3 (smem 3x69632 = 208896 B/SM).
// ============================================================================
__global__ void __launch_bounds__(TPB, 3) edge_kernel(
    const float* __restrict__ fr2_b,
    const float* __restrict__ fr3_w, const float* __restrict__ fr3_b)
{
    extern __shared__ __align__(16) unsigned char dsm[];
    __shared__ __align__(16) float SDR[HID];
    __shared__ __align__(16) float SW3p[H2 * 8];   // per o: w3[0..4], b2, 0, 0
    __shared__ float SB3[8];
    __shared__ float SRED[12 * DE];

    uint32_t* Abuf = reinterpret_cast<uint32_t*>(dsm + SM_A);
    uint32_t* Bh = reinterpret_cast<uint32_t*>(dsm + SM_B);

    const int r = blockIdx.x, b = blockIdx.y;
    const int tid = threadIdx.x, wid = tid >> 5, lane = tid & 31;
    const int gid = lane >> 2, tig = lane & 3;

    // ---- stage small operands + B ----
    {
        const uint4* sh = reinterpret_cast<const uint4*>(g_W2h);
        uint4* dh = reinterpret_cast<uint4*>(Bh);
        for (int idx = tid; idx < B_BYTES / 16; idx += TPB) dh[idx] = sh[idx];
    }
    if (tid < HID) SDR[tid] = g_DR[((size_t)b * NC + r) * HID + tid];
    for (int idx = tid; idx < H2 * 8; idx += TPB) {
        int o = idx >> 3, k = idx & 7;
        SW3p[idx] = (k < 5) ? fr3_w[o * DE + k] : (k == 5 ? fr2_b[o] : 0.f);
    }
    if (tid < DE) SB3[tid] = fr3_b[tid];
    __syncthreads();

    // ---- build A (fp16): row = tid>>1, half = tid&1 (64 floats each) ----
    {
        const int arow = tid >> 1, ahalf = tid & 1;
        uint32_t* aout = Abuf + arow * SA_U32 + ahalf * 32;
        if (arow < NC) {
            const float4* dsn4 = reinterpret_cast<const float4*>(
                g_DSn + ((size_t)b * NC + arow) * HID) + ahalf * 16;
            const float4* drp4 = reinterpret_cast<const float4*>(SDR) + ahalf * 16;
            #pragma unroll 4
            for (int g = 0; g < 16; g++) {
                float4 u = dsn4[g], p = drp4[g];
                float h0 = fmaxf(u.x + p.x, 0.f), h1 = fmaxf(u.y + p.y, 0.f);
                float h2 = fmaxf(u.z + p.z, 0.f), h3 = fmaxf(u.w + p.w, 0.f);
                uint32_t o01, o23;
                CVT2H(o01, h0, h1);
                CVT2H(o23, h2, h3);
                *reinterpret_cast<uint2*>(aout + 2 * g) = make_uint2(o01, o23);
            }
        } else {
            uint2 z = make_uint2(0u, 0u);
            #pragma unroll 4
            for (int g = 0; g < 16; g++)
                *reinterpret_cast<uint2*>(aout + 2 * g) = z;
        }
    }
    __syncthreads();

    // ---- GEMM: warp wid owns m16 tile rows [16*wid, 16*wid+16) ----
    float d[8][4];
    #pragma unroll
    for (int nt = 0; nt < 8; nt++)
        #pragma unroll
        for (int e = 0; e < 4; e++) d[nt][e] = 0.f;

    const int abase0 = (wid * 16 + gid) * SA_U32;
    #pragma unroll
    for (int kt = 0; kt < 8; kt++) {
        const int kb = kt * 8 + tig;
        uint32_t af[4];
        af[0] = Abuf[abase0 + kb];
        af[1] = Abuf[abase0 + 8 * SA_U32 + kb];
        af[2] = Abuf[abase0 + kb + 4];
        af[3] = Abuf[abase0 + 8 * SA_U32 + kb + 4];
        #pragma unroll
        for (int nt = 0; nt < 8; nt++) {
            const int bi = (nt * 8 + gid) * SA_U32 + kb;
            mma_f16(d[nt], af, Bh[bi], Bh[bi + 4]);
        }
    }

    // ---- fragment-direct epilogue: layer 3 partials ----
    float p0[DE] = {0.f, 0.f, 0.f, 0.f, 0.f};
    float p1[DE] = {0.f, 0.f, 0.f, 0.f, 0.f};
    #pragma unroll
    for (int nt = 0; nt < 8; nt++) {
        const int c = nt * 8 + tig * 2;
        float4 wA0 = *reinterpret_cast<const float4*>(SW3p + c * 8);
        float4 wB0 = *reinterpret_cast<const float4*>(SW3p + c * 8 + 4);
        float4 wA1 = *reinterpret_cast<const float4*>(SW3p + (c + 1) * 8);
        float4 wB1 = *reinterpret_cast<const float4*>(SW3p + (c + 1) * 8 + 4);
        float h00 = fmaxf(d[nt][0] + wB0.y, 0.f);
        float h01 = fmaxf(d[nt][1] + wB1.y, 0.f);
        float h10 = fmaxf(d[nt][2] + wB0.y, 0.f);
        float h11 = fmaxf(d[nt][3] + wB1.y, 0.f);
        p0[0] = fmaf(h00, wA0.x, fmaf(h01, wA1.x, p0[0]));
        p0[1] = fmaf(h00, wA0.y, fmaf(h01, wA1.y, p0[1]));
        p0[2] = fmaf(h00, wA0.z, fmaf(h01, wA1.z, p0[2]));
        p0[3] = fmaf(h00, wA0.w, fmaf(h01, wA1.w, p0[3]));
        p0[4] = fmaf(h00, wB0.x, fmaf(h01, wB1.x, p0[4]));
        p1[0] = fmaf(h10, wA0.x, fmaf(h11, wA1.x, p1[0]));
        p1[1] = fmaf(h10, wA0.y, fmaf(h11, wA1.y, p1[1]));
        p1[2] = fmaf(h10, wA0.z, fmaf(h11, wA1.z, p1[2]));
        p1[3] = fmaf(h10, wA0.w, fmaf(h11, wA1.w, p1[3]));
        p1[4] = fmaf(h10, wB0.x, fmaf(h11, wB1.x, p1[4]));
    }
    const int row0 = wid * 16 + gid, row1 = row0 + 8;
    const bool v0 = (row0 < NC) && (row0 != r);
    const bool v1 = (row1 < NC) && (row1 != r);
    #pragma unroll
    for (int k = 0; k < DE; k++) {
        float a = p0[k], c = p1[k];
        a += __shfl_xor_sync(0xffffffffu, a, 1);
        a += __shfl_xor_sync(0xffffffffu, a, 2);
        c += __shfl_xor_sync(0xffffffffu, c, 1);
        c += __shfl_xor_sync(0xffffffffu, c, 2);
        float e = (v0 ? fmaxf(SB3[k] + a, 0.f) : 0.f)
                + (v1 ? fmaxf(SB3[k] + c, 0.f) : 0.f);
        e += __shfl_down_sync(0xffffffffu, e, 16);
        e += __shfl_down_sync(0xffffffffu, e, 8);
        e += __shfl_down_sync(0xffffffffu, e, 4);
        if (lane == 0) SRED[wid * DE + k] = e;
    }
    __syncthreads();
    if (tid < DE) {
        float e = 0.f;
        #pragma unroll
        for (int w = 0; w < 12; w++) e += SRED[w * DE + tid];
        g_Ebar[((size_t)b * NC + r) * DE + tid] = e;
    }
}

// ============================================================================
// Kernel O: object MLP per node. grid (NC, BATCH), 128 threads.
// ============================================================================
__global__ void __launch_bounds__(HID) obj_kernel(
    const float* __restrict__ x,
    const float* __restrict__ fo1_w, const float* __restrict__ fo1_b,
    const float* __restrict__ fo2_w, const float* __restrict__ fo2_b,
    const float* __restrict__ fo3_w, const float* __restrict__ fo3_b)
{
    __shared__ float SC[24];        // [x(16), Ebar(5)]
    __shared__ float SH1[HID];
    __shared__ float SP2[2][H2];
    __shared__ float SH2[H2];
    const int n = blockIdx.x, b = blockIdx.y, tid = threadIdx.x;

    if (tid < PF) SC[tid] = x[((size_t)b * NC + n) * PF + tid];
    if (tid >= 32 && tid < 32 + DE)
        SC[PF + tid - 32] = g_Ebar[((size_t)b * NC + n) * DE + (tid - 32)];
    __syncthreads();

    {
        float a = fo1_b[tid];
        #pragma unroll
        for (int m = 0; m < PF + DE; m++)
            a = fmaf(SC[m], fo1_w[m * HID + tid], a);
        SH1[tid] = fmaxf(a, 0.f);
    }
    __syncthreads();

    {
        const int o = tid & (H2 - 1), p = tid >> 6;
        float a = (p == 0) ? fo2_b[o] : 0.f;
        const int m0 = p * 64;
        #pragma unroll 8
        for (int m = m0; m < m0 + 64; m++)
            a = fmaf(SH1[m], fo2_w[m * H2 + o], a);
        SP2[p][o] = a;
    }
    __syncthreads();
    if (tid < H2) SH2[tid] = fmaxf(SP2[0][tid] + SP2[1][tid], 0.f);
    __syncthreads();

    if (tid < DOUT) {
        float a = fo3_b[tid];
        #pragma unroll
        for (int m = 0; m < H2; m++)
            a = fmaf(SH2[m], fo3_w[m * DOUT + tid], a);
        g_O[((size_t)b * NC + n) * DOUT + tid] = fmaxf(a, 0.f);
    }
}

// ============================================================================
// Kernel B1: fc1 split-K partials. grid (BATCH, 16), 128 threads.
// ============================================================================
__global__ void __launch_bounds__(HID) fc1_kernel(
    const float* __restrict__ fc1_w, const float* __restrict__ fc1_b)
{
    const int b = blockIdx.x, p = blockIdx.y, o = threadIdx.x;
    const int m0 = p * 71;
    const int mend = (m0 + 71 < NC * DOUT) ? m0 + 71 : NC * DOUT;
    const float* Ob = g_O + (size_t)b * NC * DOUT;
    float a = (p == 0) ? fc1_b[o] : 0.f;
    #pragma unroll 4
    for (int m = m0; m < mend; m++)
        a = fmaf(Ob[m], fc1_w[m * HID + o], a);
    g_P1[((size_t)b * 16 + p) * HID + o] = a;
}

// ============================================================================
// Kernel B2: finish head. grid BATCH, 128 threads.
// ============================================================================
__global__ void __launch_bounds__(HID) fc2_kernel(
    const float* __restrict__ fc2_w, const float* __restrict__ fc2_b,
    const float* __restrict__ fc3_w, const float* __restrict__ fc3_b,
    float* __restrict__ out)
{
    __shared__ float sh1[HID];
    __shared__ float sp2[2][H2];
    __shared__ float sh2[H2];
    const int b = blockIdx.x, tid = threadIdx.x;

    float a = 0.f;
    #pragma unroll
    for (int p = 0; p < 16; p++)
        a += g_P1[((size_t)b * 16 + p) * HID + tid];
    sh1[tid] = fmaxf(a, 0.f);
    __syncthreads();

    {
        const int o = tid & (H2 - 1), pp = tid >> 6;
        const int m0 = pp * 64;
        float a2 = (pp == 0) ? fc2_b[o] : 0.f;
        #pragma unroll 4
        for (int m = m0; m < m0 + 64; m++)
            a2 = fmaf(sh1[m], fc2_w[m * H2 + o], a2);
        sp2[pp][o] = a2;
    }
    __syncthreads();
    if (tid < H2) sh2[tid] = fmaxf(sp2[0][tid] + sp2[1][tid], 0.f);
    __syncthreads();

    if (tid < NT) {
        float a3 = fc3_b[tid];
        #pragma unroll
        for (int m = 0; m < H2; m++)
            a3 = fmaf(sh2[m], fc3_w[m * NT + tid], a3);
        out[b * NT + tid] = a3;
    }
}

// ============================================================================
// Launch
// ============================================================================
extern "C" void kernel_launch(void* const* d_in, const int* in_sizes, int n_in,
                              void* d_out, int out_size) {
    const float* x     = (const float*)d_in[0];
    const float* fr1_w = (const float*)d_in[1];
    const float* fr1_b = (const float*)d_in[2];
    const float* fr2_w = (const float*)d_in[3];
    const float* fr2_b = (const float*)d_in[4];
    const float* fr3_w = (const float*)d_in[5];
    const float* fr3_b = (const float*)d_in[6];
    const float* fo1_w = (const float*)d_in[7];
    const float* fo1_b = (const float*)d_in[8];
    const float* fo2_w = (const float*)d_in[9];
    const float* fo2_b = (const float*)d_in[10];
    const float* fo3_w = (const float*)d_in[11];
    const float* fo3_b = (const float*)d_in[12];
    const float* fc1_w = (const float*)d_in[13];
    const float* fc1_b = (const float*)d_in[14];
    const float* fc2_w = (const float*)d_in[15];
    const float* fc2_b = (const float*)d_in[16];
    const float* fc3_w = (const float*)d_in[17];
    const float* fc3_b = (const float*)d_in[18];
    float* out = (float*)d_out;

    static bool attr_set = false;
    if (!attr_set) {
        cudaFuncSetAttribute(edge_kernel,
                             cudaFuncAttributeMaxDynamicSharedMemorySize, DYN_SMEM);
        attr_set = true;
    }

    dim3 pgrid(47, BATCH);
    precompute_kernel<<<pgrid, 512>>>(x, fr1_w, fr1_b);
    w2prep_kernel<<<32, 256>>>(fr2_w);

    dim3 grid(NC, BATCH);
    edge_kernel<<<grid, TPB, DYN_SMEM>>>(fr2_b, fr3_w, fr3_b);
    obj_kernel<<<grid, HID>>>(x, fo1_w, fo1_b, fo2_w, fo2_b, fo3_w, fo3_b);

    dim3 fgrid(BATCH, 16);
    fc1_kernel<<<fgrid, HID>>>(fc1_w, fc1_b);
    fc2_kernel<<<BATCH, HID>>>(fc2_w, fc2_b, fc3_w, fc3_b, out);
}

// round 10
// speedup vs baseline: 4.4471x; 1.8066x over previous
#include <cuda_runtime.h>
#include <cuda_bf16.h>
#include <cuda_fp16.h>
#include <cstdint>

// Problem constants
#define NC    188
#define PF    16
#define HID   128
#define H2    64
#define DE    5
#define DOUT  6
#define NT    5
#define BATCH 32
#define TPB   384   // 12 warps; one m16 tile per warp (192 rows)

// DS tile in smem: 192 rows x 136 halves (272 B = 17 uint4 = 68 u32 stride)
#define SROW_U32 68
#define SROW_U4  17
#define DS_BYTES 52224      // 192 * 272
#define B_BYTES  17408      // 64 * 272
#define SM_B     52224
#define DYN_SMEM 69632      // 3 blocks/SM

// Scratch
__device__ float g_O[BATCH * NC * DOUT];
__device__ float g_Ebar[BATCH * NC * DE];
__device__ __align__(16) __half g_DRh[BATCH * NC * HID];  // fp16 DR
__device__ __align__(16) __half g_DSh[BATCH * NC * HID];  // fp16 DS
__device__ __align__(16) __half g_W2h[H2 * 136];
__device__ float g_P1[BATCH * 16 * HID];   // fc1 split-K partials

__device__ __forceinline__ void mma_f16(float* d, const uint32_t* a,
                                        uint32_t b0, uint32_t b1) {
    asm volatile(
        "mma.sync.aligned.m16n8k16.row.col.f32.f16.f16.f32 "
        "{%0,%1,%2,%3}, {%4,%5,%6,%7}, {%8,%9}, {%0,%1,%2,%3};"
        : "+f"(d[0]), "+f"(d[1]), "+f"(d[2]), "+f"(d[3])
        : "r"(a[0]), "r"(a[1]), "r"(a[2]), "r"(a[3]), "r"(b0), "r"(b1));
}

// relu(a + b) on packed f16x2
__device__ __forceinline__ uint32_t h2_relu_add(uint32_t a, uint32_t b) {
    uint32_t r;
    asm("{\n\tadd.f16x2 %0, %1, %2;\n\tmax.f16x2 %0, %0, %3;\n\t}"
        : "=r"(r) : "r"(a), "r"(b), "r"(0u));
    return r;
}

// ============================================================================
// Kernel P: per-node layer-1 half-dots -> fp16. 4 nodes/block, 512 threads.
// ============================================================================
__global__ void __launch_bounds__(512) precompute_kernel(
    const float* __restrict__ x,
    const float* __restrict__ fr1_w, const float* __restrict__ fr1_b)
{
    __shared__ float SX[4][PF];
    const int sub = threadIdx.x >> 7;
    const int i = threadIdx.x & (HID - 1);
    const int n = blockIdx.x * 4 + sub;          // 47*4 = 188
    const int b = blockIdx.y;
    if (i < PF) SX[sub][i] = x[((size_t)b * NC + n) * PF + i];
    __syncthreads();
    float dr = fr1_b[i], ds = 0.f;
    #pragma unroll
    for (int m = 0; m < PF; m++) {
        float xm = SX[sub][m];
        dr = fmaf(xm, fr1_w[m * HID + i], dr);
        ds = fmaf(xm, fr1_w[(PF + m) * HID + i], ds);
    }
    g_DRh[((size_t)b * NC + n) * HID + i] = __float2half_rn(dr);
    g_DSh[((size_t)b * NC + n) * HID + i] = __float2half_rn(ds);
}

// ============================================================================
// Kernel W: W2^T as fp16 image [64][136]
// ============================================================================
__global__ void __launch_bounds__(256) w2prep_kernel(const float* __restrict__ fr2_w)
{
    int idx = blockIdx.x * 256 + threadIdx.x;
    if (idx < HID * H2) {
        int o = idx >> 7, k = idx & 127;
        g_W2h[o * 136 + k] = __float2half_rn(fr2_w[k * H2 + o]);
    }
}

// ============================================================================
// Kernel A: one block per (receiver r, batch b). fp16 mma.sync -> Ebar.
// A fragments computed on the fly from DS (smem) + DR (smem broadcast).
// ============================================================================
__global__ void __launch_bounds__(TPB, 3) edge_kernel(
    const float* __restrict__ fr2_b,
    const float* __restrict__ fr3_w, const float* __restrict__ fr3_b)
{
    extern __shared__ __align__(16) unsigned char dsm[];
    __shared__ __align__(16) float SW3p[H2 * 8];   // per o: w3[0..4], b2, 0, 0
    __shared__ __align__(8) uint32_t SDR16[64];    // DR as 64 f16x2 words
    __shared__ float SB3[8];
    __shared__ float SRED[12 * DE];

    const uint32_t* DS32 = reinterpret_cast<const uint32_t*>(dsm);
    const uint32_t* B32 = reinterpret_cast<const uint32_t*>(dsm + SM_B);

    const int r = blockIdx.x, b = blockIdx.y;
    const int tid = threadIdx.x, wid = tid >> 5, lane = tid & 31;
    const int gid = lane >> 2, tig = lane & 3;

    // ---- stage: DS tile (raw copy), B, DR, W3 ----
    {
        const uint4* src = reinterpret_cast<const uint4*>(
            g_DSh + (size_t)b * NC * HID);
        uint4* dst = reinterpret_cast<uint4*>(dsm);
        #pragma unroll 4
        for (int idx = tid; idx < NC * 16; idx += TPB) {   // 3008 uint4
            int row = idx >> 4, col = idx & 15;
            dst[row * SROW_U4 + col] = src[idx];
        }
        if (tid < 68) {   // pad rows 188..191 = -inf so relu -> 0
            uint4 ninf = {0xFC00FC00u, 0xFC00FC00u, 0xFC00FC00u, 0xFC00FC00u};
            int row = NC + tid / SROW_U4, col = tid % SROW_U4;
            dst[row * SROW_U4 + col] = ninf;
        }
    }
    {
        const uint4* sh = reinterpret_cast<const uint4*>(g_W2h);
        uint4* dh = reinterpret_cast<uint4*>(dsm + SM_B);
        #pragma unroll 2
        for (int idx = tid; idx < B_BYTES / 16; idx += TPB) dh[idx] = sh[idx];
    }
    if (tid < 64)
        SDR16[tid] = reinterpret_cast<const uint32_t*>(
            g_DRh + ((size_t)b * NC + r) * HID)[tid];
    for (int idx = tid; idx < H2 * 8; idx += TPB) {
        int o = idx >> 3, k = idx & 7;
        SW3p[idx] = (k < 5) ? fr3_w[o * DE + k] : (k == 5 ? fr2_b[o] : 0.f);
    }
    if (tid < DE) SB3[tid] = fr3_b[tid];
    __syncthreads();

    // ---- GEMM: warp wid owns m16 tile rows [16*wid, 16*wid+16) ----
    float d[8][4];
    #pragma unroll
    for (int nt = 0; nt < 8; nt++)
        #pragma unroll
        for (int e = 0; e < 4; e++) d[nt][e] = 0.f;

    const int abase0 = (wid * 16 + gid) * SROW_U32;
    #pragma unroll
    for (int kt = 0; kt < 8; kt++) {
        const int kb = kt * 8 + tig;
        const uint32_t dr0 = SDR16[kb], dr1 = SDR16[kb + 4];
        uint32_t af[4];
        af[0] = h2_relu_add(DS32[abase0 + kb], dr0);
        af[1] = h2_relu_add(DS32[abase0 + 8 * SROW_U32 + kb], dr0);
        af[2] = h2_relu_add(DS32[abase0 + kb + 4], dr1);
        af[3] = h2_relu_add(DS32[abase0 + 8 * SROW_U32 + kb + 4], dr1);
        #pragma unroll
        for (int nt = 0; nt < 8; nt++) {
            const int bi = (nt * 8 + gid) * SROW_U32 + kb;
            mma_f16(d[nt], af, B32[bi], B32[bi + 4]);
        }
    }

    // ---- fragment-direct epilogue: layer 3 partials ----
    float p0[DE] = {0.f, 0.f, 0.f, 0.f, 0.f};
    float p1[DE] = {0.f, 0.f, 0.f, 0.f, 0.f};
    #pragma unroll
    for (int nt = 0; nt < 8; nt++) {
        const int c = nt * 8 + tig * 2;
        float4 wA0 = *reinterpret_cast<const float4*>(SW3p + c * 8);
        float4 wB0 = *reinterpret_cast<const float4*>(SW3p + c * 8 + 4);
        float4 wA1 = *reinterpret_cast<const float4*>(SW3p + (c + 1) * 8);
        float4 wB1 = *reinterpret_cast<const float4*>(SW3p + (c + 1) * 8 + 4);
        float h00 = fmaxf(d[nt][0] + wB0.y, 0.f);
        float h01 = fmaxf(d[nt][1] + wB1.y, 0.f);
        float h10 = fmaxf(d[nt][2] + wB0.y, 0.f);
        float h11 = fmaxf(d[nt][3] + wB1.y, 0.f);
        p0[0] = fmaf(h00, wA0.x, fmaf(h01, wA1.x, p0[0]));
        p0[1] = fmaf(h00, wA0.y, fmaf(h01, wA1.y, p0[1]));
        p0[2] = fmaf(h00, wA0.z, fmaf(h01, wA1.z, p0[2]));
        p0[3] = fmaf(h00, wA0.w, fmaf(h01, wA1.w, p0[3]));
        p0[4] = fmaf(h00, wB0.x, fmaf(h01, wB1.x, p0[4]));
        p1[0] = fmaf(h10, wA0.x, fmaf(h11, wA1.x, p1[0]));
        p1[1] = fmaf(h10, wA0.y, fmaf(h11, wA1.y, p1[1]));
        p1[2] = fmaf(h10, wA0.z, fmaf(h11, wA1.z, p1[2]));
        p1[3] = fmaf(h10, wA0.w, fmaf(h11, wA1.w, p1[3]));
        p1[4] = fmaf(h10, wB0.x, fmaf(h11, wB1.x, p1[4]));
    }
    const int row0 = wid * 16 + gid, row1 = row0 + 8;
    const bool v0 = (row0 < NC) && (row0 != r);
    const bool v1 = (row1 < NC) && (row1 != r);
    #pragma unroll
    for (int k = 0; k < DE; k++) {
        float a = p0[k], c = p1[k];
        a += __shfl_xor_sync(0xffffffffu, a, 1);
        a += __shfl_xor_sync(0xffffffffu, a, 2);
        c += __shfl_xor_sync(0xffffffffu, c, 1);
        c += __shfl_xor_sync(0xffffffffu, c, 2);
        float e = (v0 ? fmaxf(SB3[k] + a, 0.f) : 0.f)
                + (v1 ? fmaxf(SB3[k] + c, 0.f) : 0.f);
        e += __shfl_down_sync(0xffffffffu, e, 16);
        e += __shfl_down_sync(0xffffffffu, e, 8);
        e += __shfl_down_sync(0xffffffffu, e, 4);
        if (lane == 0) SRED[wid * DE + k] = e;
    }
    __syncthreads();
    if (tid < DE) {
        float e = 0.f;
        #pragma unroll
        for (int w = 0; w < 12; w++) e += SRED[w * DE + tid];
        g_Ebar[((size_t)b * NC + r) * DE + tid] = e;
    }
}

// ============================================================================
// Kernel O: object MLP per node. grid (NC, BATCH), 128 threads.
// ============================================================================
__global__ void __launch_bounds__(HID) obj_kernel(
    const float* __restrict__ x,
    const float* __restrict__ fo1_w, const float* __restrict__ fo1_b,
    const float* __restrict__ fo2_w, const float* __restrict__ fo2_b,
    const float* __restrict__ fo3_w, const float* __restrict__ fo3_b)
{
    __shared__ float SC[24];
    __shared__ float SH1[HID];
    __shared__ float SP2[2][H2];
    __shared__ float SH2[H2];
    const int n = blockIdx.x, b = blockIdx.y, tid = threadIdx.x;

    if (tid < PF) SC[tid] = x[((size_t)b * NC + n) * PF + tid];
    if (tid >= 32 && tid < 32 + DE)
        SC[PF + tid - 32] = g_Ebar[((size_t)b * NC + n) * DE + (tid - 32)];
    __syncthreads();

    {
        float a = fo1_b[tid];
        #pragma unroll
        for (int m = 0; m < PF + DE; m++)
            a = fmaf(SC[m], fo1_w[m * HID + tid], a);
        SH1[tid] = fmaxf(a, 0.f);
    }
    __syncthreads();

    {
        const int o = tid & (H2 - 1), p = tid >> 6;
        float a = (p == 0) ? fo2_b[o] : 0.f;
        const int m0 = p * 64;
        #pragma unroll 8
        for (int m = m0; m < m0 + 64; m++)
            a = fmaf(SH1[m], fo2_w[m * H2 + o], a);
        SP2[p][o] = a;
    }
    __syncthreads();
    if (tid < H2) SH2[tid] = fmaxf(SP2[0][tid] + SP2[1][tid], 0.f);
    __syncthreads();

    if (tid < DOUT) {
        float a = fo3_b[tid];
        #pragma unroll
        for (int m = 0; m < H2; m++)
            a = fmaf(SH2[m], fo3_w[m * DOUT + tid], a);
        g_O[((size_t)b * NC + n) * DOUT + tid] = fmaxf(a, 0.f);
    }
}

// ============================================================================
// Kernel B1: fc1 split-K partials. grid (BATCH, 16), 128 threads.
// ============================================================================
__global__ void __launch_bounds__(HID) fc1_kernel(
    const float* __restrict__ fc1_w, const float* __restrict__ fc1_b)
{
    const int b = blockIdx.x, p = blockIdx.y, o = threadIdx.x;
    const int m0 = p * 71;
    const int mend = (m0 + 71 < NC * DOUT) ? m0 + 71 : NC * DOUT;
    const float* Ob = g_O + (size_t)b * NC * DOUT;
    float a = (p == 0) ? fc1_b[o] : 0.f;
    #pragma unroll 4
    for (int m = m0; m < mend; m++)
        a = fmaf(Ob[m], fc1_w[m * HID + o], a);
    g_P1[((size_t)b * 16 + p) * HID + o] = a;
}

// ============================================================================
// Kernel B2: finish head. grid BATCH, 128 threads.
// ============================================================================
__global__ void __launch_bounds__(HID) fc2_kernel(
    const float* __restrict__ fc2_w, const float* __restrict__ fc2_b,
    const float* __restrict__ fc3_w, const float* __restrict__ fc3_b,
    float* __restrict__ out)
{
    __shared__ float sh1[HID];
    __shared__ float sp2[2][H2];
    __shared__ float sh2[H2];
    const int b = blockIdx.x, tid = threadIdx.x;

    float a = 0.f;
    #pragma unroll
    for (int p = 0; p < 16; p++)
        a += g_P1[((size_t)b * 16 + p) * HID + tid];
    sh1[tid] = fmaxf(a, 0.f);
    __syncthreads();

    {
        const int o = tid & (H2 - 1), pp = tid >> 6;
        const int m0 = pp * 64;
        float a2 = (pp == 0) ? fc2_b[o] : 0.f;
        #pragma unroll 4
        for (int m = m0; m < m0 + 64; m++)
            a2 = fmaf(sh1[m], fc2_w[m * H2 + o], a2);
        sp2[pp][o] = a2;
    }
    __syncthreads();
    if (tid < H2) sh2[tid] = fmaxf(sp2[0][tid] + sp2[1][tid], 0.f);
    __syncthreads();

    if (tid < NT) {
        float a3 = fc3_b[tid];
        #pragma unroll
        for (int m = 0; m < H2; m++)
            a3 = fmaf(sh2[m], fc3_w[m * NT + tid], a3);
        out[b * NT + tid] = a3;
    }
}

// ============================================================================
// Launch
// ============================================================================
extern "C" void kernel_launch(void* const* d_in, const int* in_sizes, int n_in,
                              void* d_out, int out_size) {
    const float* x     = (const float*)d_in[0];
    const float* fr1_w = (const float*)d_in[1];
    const float* fr1_b = (const float*)d_in[2];
    const float* fr2_w = (const float*)d_in[3];
    const float* fr2_b = (const float*)d_in[4];
    const float* fr3_w = (const float*)d_in[5];
    const float* fr3_b = (const float*)d_in[6];
    const float* fo1_w = (const float*)d_in[7];
    const float* fo1_b = (const float*)d_in[8];
    const float* fo2_w = (const float*)d_in[9];
    const float* fo2_b = (const float*)d_in[10];
    const float* fo3_w = (const float*)d_in[11];
    const float* fo3_b = (const float*)d_in[12];
    const float* fc1_w = (const float*)d_in[13];
    const float* fc1_b = (const float*)d_in[14];
    const float* fc2_w = (const float*)d_in[15];
    const float* fc2_b = (const float*)d_in[16];
    const float* fc3_w = (const float*)d_in[17];
    const float* fc3_b = (const float*)d_in[18];
    float* out = (float*)d_out;

    static bool attr_set = false;
    if (!attr_set) {
        cudaFuncSetAttribute(edge_kernel,
                             cudaFuncAttributeMaxDynamicSharedMemorySize, DYN_SMEM);
        attr_set = true;
    }

    dim3 pgrid(47, BATCH);
    precompute_kernel<<<pgrid, 512>>>(x, fr1_w, fr1_b);
    w2prep_kernel<<<32, 256>>>(fr2_w);

    dim3 grid(NC, BATCH);
    edge_kernel<<<grid, TPB, DYN_SMEM>>>(fr2_b, fr3_w, fr3_b);
    obj_kernel<<<grid, HID>>>(x, fo1_w, fo1_b, fo2_w, fo2_b, fo3_w, fo3_b);

    dim3 fgrid(BATCH, 16);
    fc1_kernel<<<fgrid, HID>>>(fc1_w, fc1_b);
    fc2_kernel<<<BATCH, HID>>>(fc2_w, fc2_b, fc3_w, fc3_b, out);
}

// round 11
// speedup vs baseline: 4.9716x; 1.1179x over previous
#include <cuda_runtime.h>
#include <cuda_bf16.h>
#include <cuda_fp16.h>
#include <cstdint>

// Problem constants
#define NC    188
#define PF    16
#define HID   128
#define H2    64
#define DE    5
#define DOUT  6
#define NT    5
#define BATCH 32
#define TPB   384   // 12 warps; one m16 tile per warp (192 rows)
#define RPB   2     // receivers per block (DS/B staging amortized)

// DS tile in smem: 192 rows x 136 halves (272 B = 17 uint4 = 68 u32 stride)
#define SROW_U32 68
#define SROW_U4  17
#define DS_BYTES 52224      // 192 * 272
#define B_BYTES  17408      // 64 * 272
#define SM_B     52224
#define DYN_SMEM 69632      // 3 blocks/SM

// Scratch
__device__ float g_O[BATCH * NC * DOUT];
__device__ float g_Ebar[BATCH * NC * DE];
__device__ __align__(16) __half g_DRh[BATCH * NC * HID];  // fp16 DR
__device__ __align__(16) __half g_DSh[BATCH * NC * HID];  // fp16 DS
__device__ __align__(16) __half g_W2h[H2 * 136];
__device__ float g_P1[BATCH * 16 * HID];   // fc1 split-K partials

__device__ __forceinline__ void mma_f16(float* d, const uint32_t* a,
                                        uint32_t b0, uint32_t b1) {
    asm volatile(
        "mma.sync.aligned.m16n8k16.row.col.f32.f16.f16.f32 "
        "{%0,%1,%2,%3}, {%4,%5,%6,%7}, {%8,%9}, {%0,%1,%2,%3};"
        : "+f"(d[0]), "+f"(d[1]), "+f"(d[2]), "+f"(d[3])
        : "r"(a[0]), "r"(a[1]), "r"(a[2]), "r"(a[3]), "r"(b0), "r"(b1));
}

// relu(a + b) on packed f16x2
__device__ __forceinline__ uint32_t h2_relu_add(uint32_t a, uint32_t b) {
    uint32_t r;
    asm("{\n\tadd.f16x2 %0, %1, %2;\n\tmax.f16x2 %0, %0, %3;\n\t}"
        : "=r"(r) : "r"(a), "r"(b), "r"(0u));
    return r;
}

// ============================================================================
// Kernel P: per-node layer-1 half-dots -> fp16. 4 nodes/block, 512 threads.
// ============================================================================
__global__ void __launch_bounds__(512) precompute_kernel(
    const float* __restrict__ x,
    const float* __restrict__ fr1_w, const float* __restrict__ fr1_b)
{
    __shared__ float SX[4][PF];
    const int sub = threadIdx.x >> 7;
    const int i = threadIdx.x & (HID - 1);
    const int n = blockIdx.x * 4 + sub;          // 47*4 = 188
    const int b = blockIdx.y;
    if (i < PF) SX[sub][i] = x[((size_t)b * NC + n) * PF + i];
    __syncthreads();
    float dr = fr1_b[i], ds = 0.f;
    #pragma unroll
    for (int m = 0; m < PF; m++) {
        float xm = SX[sub][m];
        dr = fmaf(xm, fr1_w[m * HID + i], dr);
        ds = fmaf(xm, fr1_w[(PF + m) * HID + i], ds);
    }
    g_DRh[((size_t)b * NC + n) * HID + i] = __float2half_rn(dr);
    g_DSh[((size_t)b * NC + n) * HID + i] = __float2half_rn(ds);
}

// ============================================================================
// Kernel W: W2^T as fp16 image [64][136]
// ============================================================================
__global__ void __launch_bounds__(256) w2prep_kernel(const float* __restrict__ fr2_w)
{
    int idx = blockIdx.x * 256 + threadIdx.x;
    if (idx < HID * H2) {
        int o = idx >> 7, k = idx & 127;
        g_W2h[o * 136 + k] = __float2half_rn(fr2_w[k * H2 + o]);
    }
}

// ============================================================================
// Kernel A: one block per (receiver pair, batch). fp16 mma.sync -> Ebar.
// DS/B staged once, reused across RPB receivers (only DR switches).
// ============================================================================
__global__ void __launch_bounds__(TPB, 3) edge_kernel(
    const float* __restrict__ fr2_b,
    const float* __restrict__ fr3_w, const float* __restrict__ fr3_b)
{
    extern __shared__ __align__(16) unsigned char dsm[];
    __shared__ __align__(16) float SW3p[H2 * 8];   // per o: w3[0..4], b2, 0, 0
    __shared__ __align__(8) uint32_t SDR16[RPB][64];
    __shared__ float SB3[8];
    __shared__ float SRED[12 * DE];

    const uint32_t* DS32 = reinterpret_cast<const uint32_t*>(dsm);
    const uint32_t* B32 = reinterpret_cast<const uint32_t*>(dsm + SM_B);

    const int rbase = blockIdx.x * RPB, b = blockIdx.y;
    const int tid = threadIdx.x, wid = tid >> 5, lane = tid & 31;
    const int gid = lane >> 2, tig = lane & 3;

    // ---- stage: DS tile (raw copy), B, DR x RPB, W3 ----
    {
        const uint4* src = reinterpret_cast<const uint4*>(
            g_DSh + (size_t)b * NC * HID);
        uint4* dst = reinterpret_cast<uint4*>(dsm);
        #pragma unroll 4
        for (int idx = tid; idx < NC * 16; idx += TPB) {   // 3008 uint4
            int row = idx >> 4, col = idx & 15;
            dst[row * SROW_U4 + col] = src[idx];
        }
        if (tid < 68) {   // pad rows 188..191 = -inf so relu -> 0
            uint4 ninf = {0xFC00FC00u, 0xFC00FC00u, 0xFC00FC00u, 0xFC00FC00u};
            int row = NC + tid / SROW_U4, col = tid % SROW_U4;
            dst[row * SROW_U4 + col] = ninf;
        }
    }
    {
        const uint4* sh = reinterpret_cast<const uint4*>(g_W2h);
        uint4* dh = reinterpret_cast<uint4*>(dsm + SM_B);
        #pragma unroll 2
        for (int idx = tid; idx < B_BYTES / 16; idx += TPB) dh[idx] = sh[idx];
    }
    if (tid < RPB * 64) {
        int rr = tid >> 6, w = tid & 63;
        SDR16[rr][w] = reinterpret_cast<const uint32_t*>(
            g_DRh + ((size_t)b * NC + rbase + rr) * HID)[w];
    }
    for (int idx = tid; idx < H2 * 8; idx += TPB) {
        int o = idx >> 3, k = idx & 7;
        SW3p[idx] = (k < 5) ? fr3_w[o * DE + k] : (k == 5 ? fr2_b[o] : 0.f);
    }
    if (tid < DE) SB3[tid] = fr3_b[tid];
    __syncthreads();

    const int abase0 = (wid * 16 + gid) * SROW_U32;
    const int row0 = wid * 16 + gid, row1 = row0 + 8;

    #pragma unroll 1
    for (int rr = 0; rr < RPB; rr++) {
        const int r = rbase + rr;

        // ---- GEMM: warp wid owns m16 tile rows [16*wid, 16*wid+16) ----
        float d[8][4];
        #pragma unroll
        for (int nt = 0; nt < 8; nt++)
            #pragma unroll
            for (int e = 0; e < 4; e++) d[nt][e] = 0.f;

        #pragma unroll
        for (int kt = 0; kt < 8; kt++) {
            const int kb = kt * 8 + tig;
            const uint32_t dr0 = SDR16[rr][kb], dr1 = SDR16[rr][kb + 4];
            uint32_t af[4];
            af[0] = h2_relu_add(DS32[abase0 + kb], dr0);
            af[1] = h2_relu_add(DS32[abase0 + 8 * SROW_U32 + kb], dr0);
            af[2] = h2_relu_add(DS32[abase0 + kb + 4], dr1);
            af[3] = h2_relu_add(DS32[abase0 + 8 * SROW_U32 + kb + 4], dr1);
            #pragma unroll
            for (int nt = 0; nt < 8; nt++) {
                const int bi = (nt * 8 + gid) * SROW_U32 + kb;
                mma_f16(d[nt], af, B32[bi], B32[bi + 4]);
            }
        }

        // ---- fragment-direct epilogue: layer 3 partials ----
        float p0[DE] = {0.f, 0.f, 0.f, 0.f, 0.f};
        float p1[DE] = {0.f, 0.f, 0.f, 0.f, 0.f};
        #pragma unroll
        for (int nt = 0; nt < 8; nt++) {
            const int c = nt * 8 + tig * 2;
            float4 wA0 = *reinterpret_cast<const float4*>(SW3p + c * 8);
            float4 wB0 = *reinterpret_cast<const float4*>(SW3p + c * 8 + 4);
            float4 wA1 = *reinterpret_cast<const float4*>(SW3p + (c + 1) * 8);
            float4 wB1 = *reinterpret_cast<const float4*>(SW3p + (c + 1) * 8 + 4);
            float h00 = fmaxf(d[nt][0] + wB0.y, 0.f);
            float h01 = fmaxf(d[nt][1] + wB1.y, 0.f);
            float h10 = fmaxf(d[nt][2] + wB0.y, 0.f);
            float h11 = fmaxf(d[nt][3] + wB1.y, 0.f);
            p0[0] = fmaf(h00, wA0.x, fmaf(h01, wA1.x, p0[0]));
            p0[1] = fmaf(h00, wA0.y, fmaf(h01, wA1.y, p0[1]));
            p0[2] = fmaf(h00, wA0.z, fmaf(h01, wA1.z, p0[2]));
            p0[3] = fmaf(h00, wA0.w, fmaf(h01, wA1.w, p0[3]));
            p0[4] = fmaf(h00, wB0.x, fmaf(h01, wB1.x, p0[4]));
            p1[0] = fmaf(h10, wA0.x, fmaf(h11, wA1.x, p1[0]));
            p1[1] = fmaf(h10, wA0.y, fmaf(h11, wA1.y, p1[1]));
            p1[2] = fmaf(h10, wA0.z, fmaf(h11, wA1.z, p1[2]));
            p1[3] = fmaf(h10, wA0.w, fmaf(h11, wA1.w, p1[3]));
            p1[4] = fmaf(h10, wB0.x, fmaf(h11, wB1.x, p1[4]));
        }
        const bool v0 = (row0 < NC) && (row0 != r);
        const bool v1 = (row1 < NC) && (row1 != r);
        #pragma unroll
        for (int k = 0; k < DE; k++) {
            float a = p0[k], c = p1[k];
            a += __shfl_xor_sync(0xffffffffu, a, 1);
            a += __shfl_xor_sync(0xffffffffu, a, 2);
            c += __shfl_xor_sync(0xffffffffu, c, 1);
            c += __shfl_xor_sync(0xffffffffu, c, 2);
            float e = (v0 ? fmaxf(SB3[k] + a, 0.f) : 0.f)
                    + (v1 ? fmaxf(SB3[k] + c, 0.f) : 0.f);
            e += __shfl_down_sync(0xffffffffu, e, 16);
            e += __shfl_down_sync(0xffffffffu, e, 8);
            e += __shfl_down_sync(0xffffffffu, e, 4);
            if (lane == 0) SRED[wid * DE + k] = e;
        }
        __syncthreads();
        if (tid < DE) {
            float e = 0.f;
            #pragma unroll
            for (int w = 0; w < 12; w++) e += SRED[w * DE + tid];
            g_Ebar[((size_t)b * NC + r) * DE + tid] = e;
        }
        __syncthreads();   // SRED reused next rr
    }
}

// ============================================================================
// Kernel O: object MLP, 4 nodes/block, 128 threads; weights reused 4x/LDG.
// ============================================================================
__global__ void __launch_bounds__(HID) obj_kernel(
    const float* __restrict__ x,
    const float* __restrict__ fo1_w, const float* __restrict__ fo1_b,
    const float* __restrict__ fo2_w, const float* __restrict__ fo2_b,
    const float* __restrict__ fo3_w, const float* __restrict__ fo3_b)
{
    __shared__ float SC[4][24];      // [x(16), Ebar(5)] per node
    __shared__ float SH1[4][HID];
    __shared__ float SP2[2][4][H2];
    __shared__ float SH2[4][H2];
    const int n0 = blockIdx.x * 4, b = blockIdx.y, tid = threadIdx.x;

    if (tid < 64) {
        int sub = tid >> 4, m = tid & 15;
        SC[sub][m] = x[((size_t)b * NC + n0 + sub) * PF + m];
    } else if (tid >= 64 && tid < 64 + 20) {
        int sub = (tid - 64) / 5, k = (tid - 64) % 5;
        SC[sub][PF + k] = g_Ebar[((size_t)b * NC + n0 + sub) * DE + k];
    }
    __syncthreads();

    // fo1: 21 -> 128, weight loaded once, 4 FMAs
    {
        float a0 = fo1_b[tid], a1 = a0, a2 = a0, a3 = a0;
        #pragma unroll
        for (int m = 0; m < PF + DE; m++) {
            float w = fo1_w[m * HID + tid];
            a0 = fmaf(SC[0][m], w, a0);
            a1 = fmaf(SC[1][m], w, a1);
            a2 = fmaf(SC[2][m], w, a2);
            a3 = fmaf(SC[3][m], w, a3);
        }
        SH1[0][tid] = fmaxf(a0, 0.f);
        SH1[1][tid] = fmaxf(a1, 0.f);
        SH1[2][tid] = fmaxf(a2, 0.f);
        SH1[3][tid] = fmaxf(a3, 0.f);
    }
    __syncthreads();

    // fo2: 128 -> 64, 2-way split-K, weight loaded once, 4 FMAs
    {
        const int o = tid & (H2 - 1), p = tid >> 6;
        float bb = (p == 0) ? fo2_b[o] : 0.f;
        float a0 = bb, a1 = bb, a2 = bb, a3 = bb;
        const int m0 = p * 64;
        #pragma unroll 8
        for (int m = m0; m < m0 + 64; m++) {
            float w = fo2_w[m * H2 + o];
            a0 = fmaf(SH1[0][m], w, a0);
            a1 = fmaf(SH1[1][m], w, a1);
            a2 = fmaf(SH1[2][m], w, a2);
            a3 = fmaf(SH1[3][m], w, a3);
        }
        SP2[p][0][o] = a0; SP2[p][1][o] = a1;
        SP2[p][2][o] = a2; SP2[p][3][o] = a3;
    }
    __syncthreads();
    {
        int t = tid;                 // 128 threads cover 256 (sub,o) pairs
        #pragma unroll
        for (int rep = 0; rep < 2; rep++, t += 128) {
            int sub = t >> 6, o = t & 63;
            SH2[sub][o] = fmaxf(SP2[0][sub][o] + SP2[1][sub][o], 0.f);
        }
    }
    __syncthreads();

    // fo3: 64 -> 6, threads 0..23 (sub,oo)
    if (tid < 24) {
        const int sub = tid / 6, oo = tid % 6;
        float a = fo3_b[oo];
        #pragma unroll 8
        for (int m = 0; m < H2; m++)
            a = fmaf(SH2[sub][m], fo3_w[m * DOUT + oo], a);
        g_O[((size_t)b * NC + n0 + sub) * DOUT + oo] = fmaxf(a, 0.f);
    }
}

// ============================================================================
// Kernel B1: fc1 split-K partials. grid (BATCH, 16), 128 threads.
// ============================================================================
__global__ void __launch_bounds__(HID) fc1_kernel(
    const float* __restrict__ fc1_w, const float* __restrict__ fc1_b)
{
    const int b = blockIdx.x, p = blockIdx.y, o = threadIdx.x;
    const int m0 = p * 71;
    const int mend = (m0 + 71 < NC * DOUT) ? m0 + 71 : NC * DOUT;
    const float* Ob = g_O + (size_t)b * NC * DOUT;
    float a = (p == 0) ? fc1_b[o] : 0.f;
    #pragma unroll 4
    for (int m = m0; m < mend; m++)
        a = fmaf(Ob[m], fc1_w[m * HID + o], a);
    g_P1[((size_t)b * 16 + p) * HID + o] = a;
}

// ============================================================================
// Kernel B2: finish head. grid BATCH, 128 threads.
// ============================================================================
__global__ void __launch_bounds__(HID) fc2_kernel(
    const float* __restrict__ fc2_w, const float* __restrict__ fc2_b,
    const float* __restrict__ fc3_w, const float* __restrict__ fc3_b,
    float* __restrict__ out)
{
    __shared__ float sh1[HID];
    __shared__ float sp2[2][H2];
    __shared__ float sh2[H2];
    const int b = blockIdx.x, tid = threadIdx.x;

    float a = 0.f;
    #pragma unroll
    for (int p = 0; p < 16; p++)
        a += g_P1[((size_t)b * 16 + p) * HID + tid];
    sh1[tid] = fmaxf(a, 0.f);
    __syncthreads();

    {
        const int o = tid & (H2 - 1), pp = tid >> 6;
        const int m0 = pp * 64;
        float a2 = (pp == 0) ? fc2_b[o] : 0.f;
        #pragma unroll 4
        for (int m = m0; m < m0 + 64; m++)
            a2 = fmaf(sh1[m], fc2_w[m * H2 + o], a2);
        sp2[pp][o] = a2;
    }
    __syncthreads();
    if (tid < H2) sh2[tid] = fmaxf(sp2[0][tid] + sp2[1][tid], 0.f);
    __syncthreads();

    if (tid < NT) {
        float a3 = fc3_b[tid];
        #pragma unroll
        for (int m = 0; m < H2; m++)
            a3 = fmaf(sh2[m], fc3_w[m * NT + tid], a3);
        out[b * NT + tid] = a3;
    }
}

// ============================================================================
// Launch
// ============================================================================
extern "C" void kernel_launch(void* const* d_in, const int* in_sizes, int n_in,
                              void* d_out, int out_size) {
    const float* x     = (const float*)d_in[0];
    const float* fr1_w = (const float*)d_in[1];
    const float* fr1_b = (const float*)d_in[2];
    const float* fr2_w = (const float*)d_in[3];
    const float* fr2_b = (const float*)d_in[4];
    const float* fr3_w = (const float*)d_in[5];
    const float* fr3_b = (const float*)d_in[6];
    const float* fo1_w = (const float*)d_in[7];
    const float* fo1_b = (const float*)d_in[8];
    const float* fo2_w = (const float*)d_in[9];
    const float* fo2_b = (const float*)d_in[10];
    const float* fo3_w = (const float*)d_in[11];
    const float* fo3_b = (const float*)d_in[12];
    const float* fc1_w = (const float*)d_in[13];
    const float* fc1_b = (const float*)d_in[14];
    const float* fc2_w = (const float*)d_in[15];
    const float* fc2_b = (const float*)d_in[16];
    const float* fc3_w = (const float*)d_in[17];
    const float* fc3_b = (const float*)d_in[18];
    float* out = (float*)d_out;

    static bool attr_set = false;
    if (!attr_set) {
        cudaFuncSetAttribute(edge_kernel,
                             cudaFuncAttributeMaxDynamicSharedMemorySize, DYN_SMEM);
        attr_set = true;
    }

    dim3 pgrid(47, BATCH);
    precompute_kernel<<<pgrid, 512>>>(x, fr1_w, fr1_b);
    w2prep_kernel<<<32, 256>>>(fr2_w);

    dim3 egrid(NC / RPB, BATCH);
    edge_kernel<<<egrid, TPB, DYN_SMEM>>>(fr2_b, fr3_w, fr3_b);

    dim3 ogrid(47, BATCH);
    obj_kernel<<<ogrid, HID>>>(x, fo1_w, fo1_b, fo2_w, fo2_b, fo3_w, fo3_b);

    dim3 fgrid(BATCH, 16);
    fc1_kernel<<<fgrid, HID>>>(fc1_w, fc1_b);
    fc2_kernel<<<BATCH, HID>>>(fc2_w, fc2_b, fc3_w, fc3_b, out);
}